// round 13
// baseline (speedup 1.0000x reference)
#include <cuda_runtime.h>
#include <cstdint>

// ---------------- problem constants ----------------
constexpr int B_  = 4;
constexpr int T_  = 4096;
constexpr int C_  = 1024;
constexpr int NH_ = 16;
constexpr int HD_ = 64;
constexpr int A_  = 64;
constexpr int C3_ = 3 * C_;          // 3072
constexpr int BT_ = B_ * T_;         // 16384 rows
constexpr int BH_ = B_ * NH_;        // 64 (b,h) pairs
constexpr int NCHUNK_ = 8;           // T split for stage-1
constexpr int CT_ = T_ / NCHUNK_;    // 512 keys per chunk
constexpr int KT_ = 64;              // key tile
constexpr float SCALE_ = 0.125f;     // 1/sqrt(64)

// ---------------- scratch (device globals: no cudaMalloc allowed) ----------------
__device__ float g_qkv[(size_t)BT_ * C3_];                    // [B*T, 3C] = q | k_a | v_a
__device__ float g_w2[(size_t)C3_ * C_];                      // folded Wqkv (fp32)
__device__ float g_b2[C3_];                                   // folded bqkv
__device__ float g_xs[2 * (size_t)BT_ * C_];                  // x split: hi plane | lo plane
__device__ float g_w2s[2 * (size_t)C3_ * C_];                 // W2 split
__device__ float g_wcombs[2 * (size_t)C_ * C_];               // wcomb split
__device__ float g_c2s[2 * (size_t)BT_ * C_];                 // c2 split (written by stage2)
__device__ float g_qa[NH_ * A_ * HD_];                        // q_a (batch-independent)
__device__ float g_pm[BH_ * NCHUNK_ * A_];                    // stage-1 partial max
__device__ float g_pl[BH_ * NCHUNK_ * A_];                    // stage-1 partial sum
__device__ float g_pacc[(size_t)BH_ * NCHUNK_ * A_ * HD_];    // stage-1 partial acc
__device__ float g_c1[BH_ * A_ * HD_];                        // agent context
__device__ float g_wcomb[C_ * C_];                            // Wproj @ Wout (fp32)
__device__ float g_bcomb[C_];                                 // Wproj @ bout + bproj

// =====================================================================
// TF32 tensor-core helpers
// =====================================================================
__device__ __forceinline__ void split_tf32(float x, uint32_t& hi, uint32_t& lo) {
    uint32_t h;
    asm("cvt.rna.tf32.f32 %0, %1;" : "=r"(h) : "f"(x));
    float r = x - __uint_as_float(h);     // exact (hi = x rounded to 11 bits)
    uint32_t l;
    asm("cvt.rna.tf32.f32 %0, %1;" : "=r"(l) : "f"(r));
    hi = h; lo = l;
}

__device__ __forceinline__ void mma_tf32(float c[4], const uint32_t a[4], const uint32_t b[2]) {
    asm volatile(
        "mma.sync.aligned.m16n8k8.row.col.f32.tf32.tf32.f32 "
        "{%0,%1,%2,%3}, {%4,%5,%6,%7}, {%8,%9}, {%0,%1,%2,%3};"
        : "+f"(c[0]), "+f"(c[1]), "+f"(c[2]), "+f"(c[3])
        : "r"(a[0]), "r"(a[1]), "r"(a[2]), "r"(a[3]), "r"(b[0]), "r"(b[1]));
}

__device__ __forceinline__ void cp_async16(uint32_t saddr, const void* gaddr) {
    asm volatile("cp.async.cg.shared.global [%0], [%1], 16;" :: "r"(saddr), "l"(gaddr));
}

// element-wise hi/lo split:  in[n] -> hi plane, lo plane  (float4 per thread)
__global__ void split_kernel(const float* __restrict__ in, float* __restrict__ hi,
                             float* __restrict__ lo)
{
    const size_t i = ((size_t)blockIdx.x * 256 + threadIdx.x) * 4;
    const float4 v = *reinterpret_cast<const float4*>(in + i);
    uint32_t h0, l0, h1, l1, h2, l2, h3, l3;
    split_tf32(v.x, h0, l0); split_tf32(v.y, h1, l1);
    split_tf32(v.z, h2, l2); split_tf32(v.w, h3, l3);
    float4 hv = make_float4(__uint_as_float(h0), __uint_as_float(h1),
                            __uint_as_float(h2), __uint_as_float(h3));
    float4 lv = make_float4(__uint_as_float(l0), __uint_as_float(l1),
                            __uint_as_float(l2), __uint_as_float(l3));
    *reinterpret_cast<float4*>(hi + i) = hv;
    *reinterpret_cast<float4*>(lo + i) = lv;
}

// =====================================================================
// Pre-split TF32 GEMM:  C[M,N] = A[M,K] @ op(B) + bias
// Operands arrive as tf32 hi/lo planes (no cvt in the mainloop).
//   BTR=1 : B is [N,K] row-major (C = A @ B^T)
//   BTR=0 : B is [K,N] row-major (C = A @ B)
// BM=BN=128, BK=16, 256 threads (8 warps, 2x4), warp tile 64x32.
// 4 tiles/stage (Ahi,Alo,Bhi,Blo), stride 20 (BTR=0 B: 136) -> conflict-free.
// Double-buffered cp.async, 80KB smem -> 2 CTAs/SM.
// =====================================================================
constexpr int H_ASTR = 20;
constexpr int H_BSTR0 = 136;
constexpr int H_TILE = 128 * H_ASTR;          // 2560 floats
constexpr int H_STAGE = 4 * H_TILE;           // 10240 floats
constexpr int H_SMEM = 2 * H_STAGE * (int)sizeof(float);   // 81920 B

template<int BTR>
__device__ __forceinline__ void h_load_tile(const float* __restrict__ Ahi,
                                            const float* __restrict__ Alo,
                                            const float* __restrict__ Bhi,
                                            const float* __restrict__ Blo,
                                            float* st, int N, int K,
                                            int m0, int n0, int k0, int tid)
{
    float* sAh = st;
    float* sAl = st + H_TILE;
    float* sBh = st + 2 * H_TILE;
    float* sBl = st + 3 * H_TILE;
#pragma unroll
    for (int q = 0; q < 2; q++) {               // A: 128 rows x 16 k
        const int chunk = tid + q * 256;
        const int row = chunk >> 2, c4 = chunk & 3;
        const size_t go = (size_t)(m0 + row) * K + k0 + c4 * 4;
        const int so = row * H_ASTR + c4 * 4;
        cp_async16((uint32_t)__cvta_generic_to_shared(sAh + so), Ahi + go);
        cp_async16((uint32_t)__cvta_generic_to_shared(sAl + so), Alo + go);
    }
    if (BTR) {
#pragma unroll
        for (int q = 0; q < 2; q++) {           // B: 128 n-rows x 16 k
            const int chunk = tid + q * 256;
            const int row = chunk >> 2, c4 = chunk & 3;
            const size_t go = (size_t)(n0 + row) * K + k0 + c4 * 4;
            const int so = row * H_ASTR + c4 * 4;
            cp_async16((uint32_t)__cvta_generic_to_shared(sBh + so), Bhi + go);
            cp_async16((uint32_t)__cvta_generic_to_shared(sBl + so), Blo + go);
        }
    } else {
#pragma unroll
        for (int q = 0; q < 2; q++) {           // B: 16 k-rows x 128 n
            const int chunk = tid + q * 256;
            const int row = chunk >> 5, c4 = chunk & 31;
            const size_t go = (size_t)(k0 + row) * N + n0 + c4 * 4;
            const int so = row * H_BSTR0 + c4 * 4;
            cp_async16((uint32_t)__cvta_generic_to_shared(sBh + so), Bhi + go);
            cp_async16((uint32_t)__cvta_generic_to_shared(sBl + so), Blo + go);
        }
    }
}

template<int BTR>
__global__ __launch_bounds__(256, 2)
void gemm_split_kernel(const float* __restrict__ Ahi, const float* __restrict__ Alo,
                       const float* __restrict__ Bhi, const float* __restrict__ Blo,
                       const float* __restrict__ bias, float* __restrict__ Cm,
                       int M, int N, int K)
{
    extern __shared__ float hsm[];
    const int tid = threadIdx.x;
    const int warp = tid >> 5, lane = tid & 31;
    const int g = lane >> 2, c = lane & 3;
    const int m0w = (warp >> 2) * 64;
    const int n0w = (warp & 3) * 32;
    const int m0 = blockIdx.y * 128, n0 = blockIdx.x * 128;

    float acc[4][4][4];
#pragma unroll
    for (int mf = 0; mf < 4; mf++)
#pragma unroll
        for (int nf = 0; nf < 4; nf++)
#pragma unroll
            for (int i = 0; i < 4; i++) acc[mf][nf][i] = 0.f;

    const int nk = K >> 4;

    h_load_tile<BTR>(Ahi, Alo, Bhi, Blo, hsm, N, K, m0, n0, 0, tid);
    asm volatile("cp.async.commit_group;");

    for (int kt = 0; kt < nk; kt++) {
        float* st = hsm + (kt & 1) * H_STAGE;
        const uint32_t* sAh = reinterpret_cast<const uint32_t*>(st);
        const uint32_t* sAl = sAh + H_TILE;
        const uint32_t* sBh = sAh + 2 * H_TILE;
        const uint32_t* sBl = sAh + 3 * H_TILE;
        if (kt + 1 < nk) {
            h_load_tile<BTR>(Ahi, Alo, Bhi, Blo, hsm + ((kt + 1) & 1) * H_STAGE,
                             N, K, m0, n0, (kt + 1) * 16, tid);
            asm volatile("cp.async.commit_group;");
            asm volatile("cp.async.wait_group 1;");
        } else {
            asm volatile("cp.async.wait_group 0;");
        }
        __syncthreads();

#pragma unroll
        for (int ks = 0; ks < 2; ks++) {
            const int kb = ks * 8;
            uint32_t bhi[4][2], blo[4][2];
#pragma unroll
            for (int nf = 0; nf < 4; nf++)
#pragma unroll
                for (int i = 0; i < 2; i++) {
                    const int idx = BTR
                        ? (n0w + nf * 8 + g) * H_ASTR + kb + c + i * 4
                        : (kb + c + i * 4) * H_BSTR0 + n0w + nf * 8 + g;
                    bhi[nf][i] = sBh[idx];
                    blo[nf][i] = sBl[idx];
                }
#pragma unroll
            for (int mf = 0; mf < 4; mf++) {
                uint32_t ahi[4], alo[4];
#pragma unroll
                for (int i = 0; i < 4; i++) {
                    const int idx = (m0w + mf * 16 + g + (i & 1) * 8) * H_ASTR
                                  + kb + c + (i >> 1) * 4;
                    ahi[i] = sAh[idx];
                    alo[i] = sAl[idx];
                }
#pragma unroll
                for (int nf = 0; nf < 4; nf++) {
                    mma_tf32(acc[mf][nf], ahi, bhi[nf]);
                    mma_tf32(acc[mf][nf], alo, bhi[nf]);
                    mma_tf32(acc[mf][nf], ahi, blo[nf]);
                }
            }
        }
        __syncthreads();
    }

#pragma unroll
    for (int nf = 0; nf < 4; nf++) {
        const int col = n0 + n0w + nf * 8 + 2 * c;
        const float b0 = bias ? bias[col] : 0.f;
        const float b1 = bias ? bias[col + 1] : 0.f;
#pragma unroll
        for (int mf = 0; mf < 4; mf++) {
            const int r0 = m0 + m0w + mf * 16 + g;
            float2 v0 = make_float2(acc[mf][nf][0] + b0, acc[mf][nf][1] + b1);
            float2 v1 = make_float2(acc[mf][nf][2] + b0, acc[mf][nf][3] + b1);
            *reinterpret_cast<float2*>(Cm + (size_t)r0 * N + col) = v0;
            *reinterpret_cast<float2*>(Cm + (size_t)(r0 + 8) * N + col) = v1;
        }
    }
}

// =====================================================================
// In-loop-split TF32 GEMM (round-12 style) — used only for small wcomb.
//   BTR=0 : C = A @ B, A [M,K], B [K,N] row-major
// =====================================================================
constexpr int G_ASTR = 36;
constexpr int G_BSTR0 = 136;
constexpr int G_ATILE = 128 * G_ASTR;
constexpr int G_STAGE = G_ATILE * 2;
constexpr int G_SMEM = 2 * G_STAGE * (int)sizeof(float);   // 73728 B

__device__ __forceinline__ void g_load_tile0(const float* __restrict__ A,
                                             const float* __restrict__ Bm,
                                             float* sA, float* sB,
                                             int N, int K, int m0, int n0, int k0, int tid)
{
#pragma unroll
    for (int q = 0; q < 4; q++) {
        const int chunk = tid + q * 256;
        const int row = chunk >> 3, c16 = chunk & 7;
        cp_async16((uint32_t)__cvta_generic_to_shared(sA + row * G_ASTR + c16 * 4),
                   A + (size_t)(m0 + row) * K + k0 + c16 * 4);
    }
#pragma unroll
    for (int q = 0; q < 4; q++) {
        const int chunk = tid + q * 256;
        const int row = chunk >> 5, c16 = chunk & 31;
        cp_async16((uint32_t)__cvta_generic_to_shared(sB + row * G_BSTR0 + c16 * 4),
                   Bm + (size_t)(k0 + row) * N + n0 + c16 * 4);
    }
}

__global__ __launch_bounds__(256)
void gemm_tf32_nn_kernel(const float* __restrict__ A, const float* __restrict__ Bm,
                         float* __restrict__ Cm, int M, int N, int K)
{
    extern __shared__ float gsm[];
    const int tid = threadIdx.x;
    const int warp = tid >> 5, lane = tid & 31;
    const int g = lane >> 2, c = lane & 3;
    const int m0w = (warp >> 2) * 64;
    const int n0w = (warp & 3) * 32;
    const int m0 = blockIdx.y * 128, n0 = blockIdx.x * 128;

    float acc[4][4][4];
#pragma unroll
    for (int mf = 0; mf < 4; mf++)
#pragma unroll
        for (int nf = 0; nf < 4; nf++)
#pragma unroll
            for (int i = 0; i < 4; i++) acc[mf][nf][i] = 0.f;

    const int nk = K >> 5;
    g_load_tile0(A, Bm, gsm, gsm + G_ATILE, N, K, m0, n0, 0, tid);
    asm volatile("cp.async.commit_group;");

    for (int kt = 0; kt < nk; kt++) {
        float* sA = gsm + (kt & 1) * G_STAGE;
        float* sB = sA + G_ATILE;
        if (kt + 1 < nk) {
            float* sAn = gsm + ((kt + 1) & 1) * G_STAGE;
            g_load_tile0(A, Bm, sAn, sAn + G_ATILE, N, K, m0, n0, (kt + 1) * 32, tid);
            asm volatile("cp.async.commit_group;");
            asm volatile("cp.async.wait_group 1;");
        } else {
            asm volatile("cp.async.wait_group 0;");
        }
        __syncthreads();

#pragma unroll
        for (int ks = 0; ks < 4; ks++) {
            const int kb = ks * 8;
            uint32_t bhi[4][2], blo[4][2];
#pragma unroll
            for (int nf = 0; nf < 4; nf++)
#pragma unroll
                for (int i = 0; i < 2; i++) {
                    const float bv = sB[(kb + c + i * 4) * G_BSTR0 + n0w + nf * 8 + g];
                    split_tf32(bv, bhi[nf][i], blo[nf][i]);
                }
#pragma unroll
            for (int mf = 0; mf < 4; mf++) {
                uint32_t ahi[4], alo[4];
#pragma unroll
                for (int i = 0; i < 4; i++) {
                    const int r = m0w + mf * 16 + g + (i & 1) * 8;
                    const int cc = kb + c + (i >> 1) * 4;
                    split_tf32(sA[r * G_ASTR + cc], ahi[i], alo[i]);
                }
#pragma unroll
                for (int nf = 0; nf < 4; nf++) {
                    mma_tf32(acc[mf][nf], ahi, bhi[nf]);
                    mma_tf32(acc[mf][nf], alo, bhi[nf]);
                    mma_tf32(acc[mf][nf], ahi, blo[nf]);
                }
            }
        }
        __syncthreads();
    }

#pragma unroll
    for (int nf = 0; nf < 4; nf++) {
        const int col = n0 + n0w + nf * 8 + 2 * c;
#pragma unroll
        for (int mf = 0; mf < 4; mf++) {
            const int r0 = m0 + m0w + mf * 16 + g;
            float2 v0 = make_float2(acc[mf][nf][0], acc[mf][nf][1]);
            float2 v1 = make_float2(acc[mf][nf][2], acc[mf][nf][3]);
            *reinterpret_cast<float2*>(Cm + (size_t)r0 * N + col) = v0;
            *reinterpret_cast<float2*>(Cm + (size_t)(r0 + 8) * N + col) = v1;
        }
    }
}

// =====================================================================
// Weight folding: W2 K/V sections = per-head Wk/Wv @ Wqkv block
// =====================================================================
__global__ __launch_bounds__(256)
void wfold_kernel(const float* __restrict__ Wqkv, const float* __restrict__ Wk,
                  const float* __restrict__ Wv, float* __restrict__ W2)
{
    __shared__ float sW[64 * 65];
    __shared__ float sQ[64 * 65];
    const int tid = threadIdx.x;
    const int tx = tid & 15, ty = tid >> 4;
    const int j0 = blockIdx.x * 64;
    const int sec = blockIdx.y;
    const int kv = sec >> 4, h = sec & 15;
    const float* Wsub = kv ? Wv : Wk;
    const size_t rowbase = (size_t)(C_ + kv * C_ + h * 64);

    for (int idx = tid; idx < 4096; idx += 256) {
        const int r = idx >> 6, cc = idx & 63;
        sW[r * 65 + cc] = Wsub[idx];
        sQ[r * 65 + cc] = Wqkv[(rowbase + r) * C_ + j0 + cc];
    }
    __syncthreads();

    float acc[4][4];
#pragma unroll
    for (int r = 0; r < 4; r++)
#pragma unroll
        for (int c = 0; c < 4; c++) acc[r][c] = 0.f;
#pragma unroll 8
    for (int e = 0; e < 64; e++) {
        float wf[4], qf[4];
#pragma unroll
        for (int r = 0; r < 4; r++) wf[r] = sW[(ty + 16*r) * 65 + e];
#pragma unroll
        for (int c = 0; c < 4; c++) qf[c] = sQ[e * 65 + tx + 16*c];
#pragma unroll
        for (int r = 0; r < 4; r++)
#pragma unroll
            for (int c = 0; c < 4; c++) acc[r][c] = fmaf(wf[r], qf[c], acc[r][c]);
    }
#pragma unroll
    for (int r = 0; r < 4; r++)
#pragma unroll
        for (int c = 0; c < 4; c++)
            W2[(rowbase + ty + 16*r) * C_ + j0 + tx + 16*c] = acc[r][c];
}

// copy Q section of Wqkv into W2 (rows 0..C)
__global__ void copyq_kernel(const float* __restrict__ Wqkv, float* __restrict__ W2)
{
    const size_t i = (size_t)blockIdx.x * 256 + threadIdx.x;
    reinterpret_cast<float4*>(W2)[i] = reinterpret_cast<const float4*>(Wqkv)[i];
}

// folded bias b2 (3C)
__global__ void b2fold_kernel(const float* __restrict__ bqkv, const float* __restrict__ Wk,
                              const float* __restrict__ bk, const float* __restrict__ Wv,
                              const float* __restrict__ bv, float* __restrict__ b2)
{
    const int i = blockIdx.x * 256 + threadIdx.x;
    if (i < C_) { b2[i] = bqkv[i]; return; }
    const int kv = (i - C_) / C_;
    const int d = (i - C_) - kv * C_;
    const int h = d >> 6, dd = d & 63;
    const float* W = kv ? Wv : Wk;
    const float* bb = kv ? bv : bk;
    float s = bb[dd];
    for (int e = 0; e < 64; e++)
        s = fmaf(W[dd * 64 + e], bqkv[C_ + kv * C_ + h * 64 + e], s);
    b2[i] = s;
}

// =====================================================================
// q_a[h] = agent_tokens[h] @ Wq^T + bq
// =====================================================================
__global__ __launch_bounds__(256)
void qa_kernel(const float* __restrict__ ag, const float* __restrict__ Wq,
               const float* __restrict__ bq, float* __restrict__ qa)
{
    __shared__ float sA[64 * 65];
    __shared__ float sW[64 * 65];
    const int tid = threadIdx.x;
    const int tx = tid & 15, ty = tid >> 4;
    const int h = blockIdx.x;

    for (int idx = tid; idx < 4096; idx += 256) {
        sA[(idx >> 6) * 65 + (idx & 63)] = ag[h * 4096 + idx];
        sW[(idx >> 6) * 65 + (idx & 63)] = Wq[idx];
    }
    __syncthreads();

    float acc[4][4];
#pragma unroll
    for (int r = 0; r < 4; r++)
#pragma unroll
        for (int c = 0; c < 4; c++) acc[r][c] = bq[tx + 16*c];
#pragma unroll 8
    for (int e = 0; e < 64; e++) {
        float af[4], wf[4];
#pragma unroll
        for (int r = 0; r < 4; r++) af[r] = sA[(ty + 16*r) * 65 + e];
#pragma unroll
        for (int c = 0; c < 4; c++) wf[c] = sW[(tx + 16*c) * 65 + e];
#pragma unroll
        for (int r = 0; r < 4; r++)
#pragma unroll
            for (int c = 0; c < 4; c++) acc[r][c] = fmaf(af[r], wf[c], acc[r][c]);
    }
#pragma unroll
    for (int r = 0; r < 4; r++)
#pragma unroll
        for (int c = 0; c < 4; c++)
            qa[h * 4096 + (ty + 16*r) * 64 + tx + 16*c] = acc[r][c];
}

// b' = Wproj @ bout + bproj
__global__ void bcomb_kernel(const float* __restrict__ Wproj, const float* __restrict__ bout,
                             const float* __restrict__ bproj, float* __restrict__ bcomb)
{
    const int i = blockIdx.x * 256 + threadIdx.x;
    float s = bproj[i];
    for (int k = 0; k < C_; k++) s = fmaf(Wproj[(size_t)i * C_ + k], bout[k], s);
    bcomb[i] = s;
}

// =====================================================================
// Stage 1 (lean): k_a/v_a pre-projected in qkv buffer.
// =====================================================================
constexpr int S1P = 65;
constexpr int S1_SMEM = 4 * 64 * S1P * (int)sizeof(float);   // 66560 B

__global__ __launch_bounds__(256)
void stage1_kernel(const float* __restrict__ qkv, const float* __restrict__ qa,
                   float* __restrict__ pm, float* __restrict__ pl,
                   float* __restrict__ pacc)
{
    extern __shared__ float sm1[];
    float* sQa = sm1;
    float* sK  = sQa + 64 * S1P;
    float* sV  = sK  + 64 * S1P;
    float* sP  = sV  + 64 * S1P;

    const int tid = threadIdx.x;
    const int tx = tid & 15, ty = tid >> 4;
    const int chunk = blockIdx.x, bh = blockIdx.y;
    const int b = bh >> 4, h = bh & 15;

    for (int idx = tid; idx < 4096; idx += 256)
        sQa[(idx >> 6) * S1P + (idx & 63)] = qa[h * 4096 + idx];

    float m_run[4], l_run[4], acc[4][4];
#pragma unroll
    for (int r = 0; r < 4; r++) {
        m_run[r] = -1e30f; l_run[r] = 0.f;
#pragma unroll
        for (int c = 0; c < 4; c++) acc[r][c] = 0.f;
    }

    const size_t rowbase = (size_t)(b * T_) * C3_;

    for (int kt = 0; kt < CT_ / KT_; kt++) {
        const int t0 = chunk * CT_ + kt * KT_;

        for (int idx = tid; idx < 1024; idx += 256) {
            const int row = idx >> 4, c4 = idx & 15;
            const size_t base = rowbase + (size_t)(t0 + row) * C3_ + h * 64 + c4 * 4;
            const float4 kv4 = *reinterpret_cast<const float4*>(qkv + base + C_);
            const float4 vv4 = *reinterpret_cast<const float4*>(qkv + base + 2 * C_);
            float* dk = &sK[row * S1P + c4 * 4];
            float* dv = &sV[row * S1P + c4 * 4];
            dk[0] = kv4.x; dk[1] = kv4.y; dk[2] = kv4.z; dk[3] = kv4.w;
            dv[0] = vv4.x; dv[1] = vv4.y; dv[2] = vv4.z; dv[3] = vv4.w;
        }
        __syncthreads();

        {
            float s[4][4];
#pragma unroll
            for (int r = 0; r < 4; r++)
#pragma unroll
                for (int c = 0; c < 4; c++) s[r][c] = 0.f;
#pragma unroll 8
            for (int e = 0; e < 64; e++) {
                float qf[4], kf[4];
#pragma unroll
                for (int r = 0; r < 4; r++) qf[r] = sQa[(ty + 16*r) * S1P + e];
#pragma unroll
                for (int c = 0; c < 4; c++) kf[c] = sK[(tx + 16*c) * S1P + e];
#pragma unroll
                for (int r = 0; r < 4; r++)
#pragma unroll
                    for (int c = 0; c < 4; c++) s[r][c] = fmaf(qf[r], kf[c], s[r][c]);
            }
#pragma unroll
            for (int r = 0; r < 4; r++) {
                float mt = -1e30f;
#pragma unroll
                for (int c = 0; c < 4; c++) { s[r][c] *= SCALE_; mt = fmaxf(mt, s[r][c]); }
#pragma unroll
                for (int ms = 8; ms >= 1; ms >>= 1)
                    mt = fmaxf(mt, __shfl_xor_sync(0xffffffffu, mt, ms));
                const float mn = fmaxf(m_run[r], mt);
                const float corr = __expf(m_run[r] - mn);
                float rs = 0.f;
#pragma unroll
                for (int c = 0; c < 4; c++) {
                    const float p = __expf(s[r][c] - mn);
                    sP[(ty + 16*r) * S1P + tx + 16*c] = p;
                    rs += p;
                }
#pragma unroll
                for (int ms = 8; ms >= 1; ms >>= 1)
                    rs += __shfl_xor_sync(0xffffffffu, rs, ms);
                l_run[r] = l_run[r] * corr + rs;
                m_run[r] = mn;
#pragma unroll
                for (int c = 0; c < 4; c++) acc[r][c] *= corr;
            }
        }
        __syncthreads();

#pragma unroll 8
        for (int t = 0; t < 64; t++) {
            float pf[4], vf[4];
#pragma unroll
            for (int r = 0; r < 4; r++) pf[r] = sP[(ty + 16*r) * S1P + t];
#pragma unroll
            for (int c = 0; c < 4; c++) vf[c] = sV[t * S1P + tx + 16*c];
#pragma unroll
            for (int r = 0; r < 4; r++)
#pragma unroll
                for (int c = 0; c < 4; c++) acc[r][c] = fmaf(pf[r], vf[c], acc[r][c]);
        }
        __syncthreads();
    }

    const int pi = bh * NCHUNK_ + chunk;
    if (tx == 0) {
#pragma unroll
        for (int r = 0; r < 4; r++) {
            pm[pi * 64 + ty + 16*r] = m_run[r];
            pl[pi * 64 + ty + 16*r] = l_run[r];
        }
    }
#pragma unroll
    for (int r = 0; r < 4; r++)
#pragma unroll
        for (int c = 0; c < 4; c++)
            pacc[(size_t)pi * 4096 + (ty + 16*r) * 64 + tx + 16*c] = acc[r][c];
}

// combine split-T partials -> c1[b,h,a,d]
__global__ __launch_bounds__(256)
void s1combine_kernel(const float* __restrict__ pm, const float* __restrict__ pl,
                      const float* __restrict__ pacc, float* __restrict__ c1)
{
    const int bh = blockIdx.x;
    const int tid = threadIdx.x;
    const int a = tid >> 2, dg = tid & 3;

    float mc[NCHUNK_], lc[NCHUNK_];
    float m = -1e30f;
#pragma unroll
    for (int c = 0; c < NCHUNK_; c++) {
        mc[c] = pm[(bh * NCHUNK_ + c) * 64 + a];
        lc[c] = pl[(bh * NCHUNK_ + c) * 64 + a];
        m = fmaxf(m, mc[c]);
    }
    float l = 0.f, w[NCHUNK_];
#pragma unroll
    for (int c = 0; c < NCHUNK_; c++) { w[c] = __expf(mc[c] - m); l += lc[c] * w[c]; }
    const float inv = 1.f / l;
#pragma unroll
    for (int j = 0; j < 16; j++) {
        const int d = dg * 16 + j;
        float s = 0.f;
#pragma unroll
        for (int c = 0; c < NCHUNK_; c++)
            s += pacc[(size_t)(bh * NCHUNK_ + c) * 4096 + a * 64 + d] * w[c];
        c1[bh * 4096 + a * 64 + d] = s * inv;
    }
}

// =====================================================================
// Stage 2: per (b,h, 128-token tile). Emits s2 + c2 in hi/lo split form.
// =====================================================================
constexpr int S2P = 65;
constexpr int S2_SMEM = (64 + 128 + 128) * S2P * (int)sizeof(float);  // 83200 B

__global__ __launch_bounds__(256)
void stage2_kernel(const float* __restrict__ qkv, const float* __restrict__ c1,
                   float* __restrict__ s2out, float* __restrict__ c2hi,
                   float* __restrict__ c2lo)
{
    extern __shared__ float sm2[];
    float* sC1 = sm2;
    float* sQ  = sC1 + 64 * S2P;
    float* sP  = sQ + 128 * S2P;

    const int tid = threadIdx.x;
    const int tx = tid & 15, ty = tid >> 4;
    const int bh = blockIdx.y;
    const int b = bh >> 4, h = bh & 15;
    const int t0 = blockIdx.x * 128;

    for (int idx = tid; idx < 4096; idx += 256)
        sC1[(idx >> 6) * S2P + (idx & 63)] = c1[bh * 4096 + idx];
    for (int idx = tid; idx < 2048; idx += 256) {
        const int row = idx >> 4, c4 = idx & 15;
        const float4 v = *reinterpret_cast<const float4*>(
            qkv + (size_t)(b * T_ + t0 + row) * C3_ + h * 64 + c4 * 4);
        float* d = &sQ[row * S2P + c4 * 4];
        d[0] = v.x; d[1] = v.y; d[2] = v.z; d[3] = v.w;
    }
    __syncthreads();

    float s[8][4];
#pragma unroll
    for (int r = 0; r < 8; r++)
#pragma unroll
        for (int c = 0; c < 4; c++) s[r][c] = 0.f;
#pragma unroll 8
    for (int d = 0; d < 64; d++) {
        float qf[8], cf[4];
#pragma unroll
        for (int r = 0; r < 8; r++) qf[r] = sQ[(ty + 16*r) * S2P + d];
#pragma unroll
        for (int c = 0; c < 4; c++) cf[c] = sC1[(tx + 16*c) * S2P + d];
#pragma unroll
        for (int r = 0; r < 8; r++)
#pragma unroll
            for (int c = 0; c < 4; c++) s[r][c] = fmaf(qf[r], cf[c], s[r][c]);
    }

#pragma unroll
    for (int r = 0; r < 8; r++) {
        float mt = -1e30f;
#pragma unroll
        for (int c = 0; c < 4; c++) { s[r][c] *= SCALE_; mt = fmaxf(mt, s[r][c]); }
#pragma unroll
        for (int ms = 8; ms >= 1; ms >>= 1)
            mt = fmaxf(mt, __shfl_xor_sync(0xffffffffu, mt, ms));
        float rs = 0.f;
#pragma unroll
        for (int c = 0; c < 4; c++) { s[r][c] = __expf(s[r][c] - mt); rs += s[r][c]; }
#pragma unroll
        for (int ms = 8; ms >= 1; ms >>= 1)
            rs += __shfl_xor_sync(0xffffffffu, rs, ms);
        const float inv = 1.f / rs;
        const int t = t0 + ty + 16*r;
        const size_t so = ((size_t)bh * T_ + t) * 64;
#pragma unroll
        for (int c = 0; c < 4; c++) {
            const float p = s[r][c] * inv;
            sP[(ty + 16*r) * S2P + tx + 16*c] = p;
            s2out[so + tx + 16*c] = p;
        }
    }
    __syncthreads();

    float acc[8][4];
#pragma unroll
    for (int r = 0; r < 8; r++)
#pragma unroll
        for (int c = 0; c < 4; c++) acc[r][c] = 0.f;
#pragma unroll 8
    for (int a = 0; a < 64; a++) {
        float pf[8], cf[4];
#pragma unroll
        for (int r = 0; r < 8; r++) pf[r] = sP[(ty + 16*r) * S2P + a];
#pragma unroll
        for (int c = 0; c < 4; c++) cf[c] = sC1[a * S2P + tx + 16*c];
#pragma unroll
        for (int r = 0; r < 8; r++)
#pragma unroll
            for (int c = 0; c < 4; c++) acc[r][c] = fmaf(pf[r], cf[c], acc[r][c]);
    }
#pragma unroll
    for (int r = 0; r < 8; r++) {
        const int t = t0 + ty + 16*r;
#pragma unroll
        for (int c = 0; c < 4; c++) {
            uint32_t h32, l32;
            split_tf32(acc[r][c], h32, l32);
            const size_t oi = (size_t)(b * T_ + t) * C_ + h * 64 + tx + 16*c;
            c2hi[oi] = __uint_as_float(h32);
            c2lo[oi] = __uint_as_float(l32);
        }
    }
}

// =====================================================================
// launch
// =====================================================================
extern "C" void kernel_launch(void* const* d_in, const int* in_sizes, int n_in,
                              void* d_out, int out_size)
{
    (void)in_sizes; (void)n_in; (void)out_size;
    const float* x     = (const float*)d_in[0];
    const float* Wqkv  = (const float*)d_in[1];
    const float* bqkv  = (const float*)d_in[2];
    const float* Wq    = (const float*)d_in[3];
    const float* bq    = (const float*)d_in[4];
    const float* Wk    = (const float*)d_in[5];
    const float* bk    = (const float*)d_in[6];
    const float* Wv    = (const float*)d_in[7];
    const float* bv    = (const float*)d_in[8];
    const float* ag    = (const float*)d_in[9];
    const float* Wout  = (const float*)d_in[10];
    const float* bout  = (const float*)d_in[11];
    const float* Wproj = (const float*)d_in[12];
    const float* bproj = (const float*)d_in[13];
    float* out = (float*)d_out;

    float *qkv, *w2, *b2, *xs, *w2s, *wcombs, *c2s, *qa, *pm, *pl, *pacc, *c1, *wcomb, *bcomb;
    cudaGetSymbolAddress((void**)&qkv,    g_qkv);
    cudaGetSymbolAddress((void**)&w2,     g_w2);
    cudaGetSymbolAddress((void**)&b2,     g_b2);
    cudaGetSymbolAddress((void**)&xs,     g_xs);
    cudaGetSymbolAddress((void**)&w2s,    g_w2s);
    cudaGetSymbolAddress((void**)&wcombs, g_wcombs);
    cudaGetSymbolAddress((void**)&c2s,    g_c2s);
    cudaGetSymbolAddress((void**)&qa,     g_qa);
    cudaGetSymbolAddress((void**)&pm,     g_pm);
    cudaGetSymbolAddress((void**)&pl,     g_pl);
    cudaGetSymbolAddress((void**)&pacc,   g_pacc);
    cudaGetSymbolAddress((void**)&c1,     g_c1);
    cudaGetSymbolAddress((void**)&wcomb,  g_wcomb);
    cudaGetSymbolAddress((void**)&bcomb,  g_bcomb);

    const size_t XPL  = (size_t)BT_ * C_;     // x / c2 plane size
    const size_t WPL  = (size_t)C3_ * C_;     // W2 plane size
    const size_t WCPL = (size_t)C_ * C_;      // wcomb plane size

    cudaFuncSetAttribute(gemm_split_kernel<1>, cudaFuncAttributeMaxDynamicSharedMemorySize, H_SMEM);
    cudaFuncSetAttribute(gemm_split_kernel<0>, cudaFuncAttributeMaxDynamicSharedMemorySize, H_SMEM);
    cudaFuncSetAttribute(gemm_tf32_nn_kernel, cudaFuncAttributeMaxDynamicSharedMemorySize, G_SMEM);
    cudaFuncSetAttribute(stage1_kernel, cudaFuncAttributeMaxDynamicSharedMemorySize, S1_SMEM);
    cudaFuncSetAttribute(stage2_kernel, cudaFuncAttributeMaxDynamicSharedMemorySize, S2_SMEM);

    // 0. fold per-head Wk/Wv into Wqkv (W2, b2); split x and W2 into tf32 hi/lo planes
    copyq_kernel<<<C_ * C_ / (256 * 4), 256>>>(Wqkv, w2);
    wfold_kernel<<<dim3(C_/64, 2*NH_), 256>>>(Wqkv, Wk, Wv, w2);
    b2fold_kernel<<<C3_/256, 256>>>(bqkv, Wk, bk, Wv, bv, b2);
    split_kernel<<<(int)(XPL / 1024), 256>>>(x, xs, xs + XPL);
    split_kernel<<<(int)(WPL / 1024), 256>>>(w2, w2s, w2s + WPL);
    // 1. qkv = x @ W2^T + b2  ->  [q | k_a | v_a]   (pre-split tensor-core GEMM)
    gemm_split_kernel<1><<<dim3(C3_/128, BT_/128), 256, H_SMEM>>>(
        xs, xs + XPL, w2s, w2s + WPL, b2, qkv, BT_, C3_, C_);
    // 2. q_a (per-head), combined bias, combined weight wcomb = Wproj @ Wout (+ split)
    qa_kernel<<<NH_, 256>>>(ag, Wq, bq, qa);
    bcomb_kernel<<<C_/256, 256>>>(Wproj, bout, bproj, bcomb);
    gemm_tf32_nn_kernel<<<dim3(C_/128, C_/128), 256, G_SMEM>>>(Wproj, Wout, wcomb, C_, C_, C_);
    split_kernel<<<(int)(WCPL / 1024), 256>>>(wcomb, wcombs, wcombs + WCPL);
    // 3. stage-1 attention (pre-projected k_a/v_a, split-T online softmax)
    stage1_kernel<<<dim3(NCHUNK_, BH_), 256, S1_SMEM>>>(qkv, qa, pm, pl, pacc);
    s1combine_kernel<<<BH_, 256>>>(pm, pl, pacc, c1);
    // 4. stage-2 attention -> s2 (output #2) + c2 (hi/lo split)
    stage2_kernel<<<dim3(T_/128, BH_), 256, S2_SMEM>>>(
        qkv, c1, out + (size_t)BT_ * C_, c2s, c2s + XPL);
    // 5. y = c2 @ (Wproj@Wout)^T + b'  -> output #1  (pre-split tensor-core GEMM)
    gemm_split_kernel<1><<<dim3(C_/128, BT_/128), 256, H_SMEM>>>(
        c2s, c2s + XPL, wcombs, wcombs + WCPL, bcomb, out, BT_, C_, C_);
}

// round 14
// speedup vs baseline: 1.1841x; 1.1841x over previous
#include <cuda_runtime.h>
#include <cstdint>

// ---------------- problem constants ----------------
constexpr int B_  = 4;
constexpr int T_  = 4096;
constexpr int C_  = 1024;
constexpr int NH_ = 16;
constexpr int HD_ = 64;
constexpr int A_  = 64;
constexpr int C3_ = 3 * C_;          // 3072
constexpr int BT_ = B_ * T_;         // 16384 rows
constexpr int BH_ = B_ * NH_;        // 64 (b,h) pairs
constexpr int NCHUNK_ = 8;           // T split for stage-1
constexpr int CT_ = T_ / NCHUNK_;    // 512 keys per chunk
constexpr int KT_ = 64;              // key tile
constexpr float SCALE_ = 0.125f;     // 1/sqrt(64)

// ---------------- scratch (device globals: no cudaMalloc allowed) ----------------
__device__ float g_qkv[(size_t)BT_ * C3_];                    // [B*T, 3C] = q | k_a | v_a
__device__ float g_w2[(size_t)C3_ * C_];                      // folded Wqkv
__device__ float g_b2[C3_];                                   // folded bqkv
__device__ float g_qa[NH_ * A_ * HD_];                        // q_a (batch-independent)
__device__ float g_pm[BH_ * NCHUNK_ * A_];                    // stage-1 partial max
__device__ float g_pl[BH_ * NCHUNK_ * A_];                    // stage-1 partial sum
__device__ float g_pacc[(size_t)BH_ * NCHUNK_ * A_ * HD_];    // stage-1 partial acc
__device__ float g_c1[BH_ * A_ * HD_];                        // agent context
__device__ float g_c2[(size_t)BT_ * C_];                      // token context [B*T, C]
__device__ float g_wcomb[C_ * C_];                            // Wproj @ Wout
__device__ float g_bcomb[C_];                                 // Wproj @ bout + bproj

// =====================================================================
// TF32 tensor-core helpers
// =====================================================================
__device__ __forceinline__ void split_tf32(float x, uint32_t& hi, uint32_t& lo) {
    uint32_t h;
    asm("cvt.rna.tf32.f32 %0, %1;" : "=r"(h) : "f"(x));
    float r = x - __uint_as_float(h);     // exact (hi = x rounded to 11 bits)
    uint32_t l;
    asm("cvt.rna.tf32.f32 %0, %1;" : "=r"(l) : "f"(r));
    hi = h; lo = l;
}

__device__ __forceinline__ void mma_tf32(float c[4], const uint32_t a[4], const uint32_t b[2]) {
    asm volatile(
        "mma.sync.aligned.m16n8k8.row.col.f32.tf32.tf32.f32 "
        "{%0,%1,%2,%3}, {%4,%5,%6,%7}, {%8,%9}, {%0,%1,%2,%3};"
        : "+f"(c[0]), "+f"(c[1]), "+f"(c[2]), "+f"(c[3])
        : "r"(a[0]), "r"(a[1]), "r"(a[2]), "r"(a[3]), "r"(b[0]), "r"(b[1]));
}

__device__ __forceinline__ void cp_async16(uint32_t saddr, const void* gaddr) {
    asm volatile("cp.async.cg.shared.global [%0], [%1], 16;" :: "r"(saddr), "l"(gaddr));
}

// =====================================================================
// TF32 split GEMM:  C[M,N] = A[M,K] @ op(B) + bias   (fp32-accuracy via 3xTF32)
//   BTR=1 : B is [N,K] row-major (C = A @ B^T)
//   BTR=0 : B is [K,N] row-major (C = A @ B)
// BM=BN=128, BK=32, 256 threads (8 warps, 2x4), warp tile 64x32.
// __launch_bounds__(256,2): cap regs at 128 so 2 CTAs/SM co-reside
// (smem 73.7KB x 2 = 147KB < 228KB). Round-12 showed regs=138 -> 1 CTA/SM,
// occ 12.5%, tensor pipe starved at 57%.
// =====================================================================
constexpr int G_ASTR = 36;
constexpr int G_BSTR0 = 136;
constexpr int G_ATILE = 128 * G_ASTR;      // 4608 floats
constexpr int G_STAGE = G_ATILE * 2;
constexpr int G_SMEM = 2 * G_STAGE * (int)sizeof(float);   // 73728 B

template<int BTR>
__device__ __forceinline__ void g_load_tile(const float* __restrict__ A,
                                            const float* __restrict__ Bm,
                                            float* sA, float* sB,
                                            int N, int K, int m0, int n0, int k0, int tid)
{
#pragma unroll
    for (int q = 0; q < 4; q++) {               // A tile: 128 rows x 32 k
        const int chunk = tid + q * 256;
        const int row = chunk >> 3, c16 = chunk & 7;
        cp_async16((uint32_t)__cvta_generic_to_shared(sA + row * G_ASTR + c16 * 4),
                   A + (size_t)(m0 + row) * K + k0 + c16 * 4);
    }
    if (BTR) {
#pragma unroll
        for (int q = 0; q < 4; q++) {           // B tile: 128 n-rows x 32 k
            const int chunk = tid + q * 256;
            const int row = chunk >> 3, c16 = chunk & 7;
            cp_async16((uint32_t)__cvta_generic_to_shared(sB + row * G_ASTR + c16 * 4),
                       Bm + (size_t)(n0 + row) * K + k0 + c16 * 4);
        }
    } else {
#pragma unroll
        for (int q = 0; q < 4; q++) {           // B tile: 32 k-rows x 128 n
            const int chunk = tid + q * 256;
            const int row = chunk >> 5, c16 = chunk & 31;
            cp_async16((uint32_t)__cvta_generic_to_shared(sB + row * G_BSTR0 + c16 * 4),
                       Bm + (size_t)(k0 + row) * N + n0 + c16 * 4);
        }
    }
}

template<int BTR>
__global__ __launch_bounds__(256, 2)
void gemm_tf32_kernel(const float* __restrict__ A, const float* __restrict__ Bm,
                      const float* __restrict__ bias, float* __restrict__ Cm,
                      int M, int N, int K)
{
    extern __shared__ float gsm[];
    const int tid = threadIdx.x;
    const int warp = tid >> 5, lane = tid & 31;
    const int g = lane >> 2, c = lane & 3;
    const int m0w = (warp >> 2) * 64;
    const int n0w = (warp & 3) * 32;
    const int m0 = blockIdx.y * 128, n0 = blockIdx.x * 128;

    float acc[4][4][4];
#pragma unroll
    for (int mf = 0; mf < 4; mf++)
#pragma unroll
        for (int nf = 0; nf < 4; nf++)
#pragma unroll
            for (int i = 0; i < 4; i++) acc[mf][nf][i] = 0.f;

    const int nk = K >> 5;

    g_load_tile<BTR>(A, Bm, gsm, gsm + G_ATILE, N, K, m0, n0, 0, tid);
    asm volatile("cp.async.commit_group;");

    for (int kt = 0; kt < nk; kt++) {
        float* sA = gsm + (kt & 1) * G_STAGE;
        float* sB = sA + G_ATILE;
        if (kt + 1 < nk) {
            float* sAn = gsm + ((kt + 1) & 1) * G_STAGE;
            g_load_tile<BTR>(A, Bm, sAn, sAn + G_ATILE, N, K, m0, n0, (kt + 1) * 32, tid);
            asm volatile("cp.async.commit_group;");
            asm volatile("cp.async.wait_group 1;");
        } else {
            asm volatile("cp.async.wait_group 0;");
        }
        __syncthreads();

#pragma unroll
        for (int ks = 0; ks < 4; ks++) {
            const int kb = ks * 8;
            uint32_t bhi[4][2], blo[4][2];
#pragma unroll
            for (int nf = 0; nf < 4; nf++)
#pragma unroll
                for (int i = 0; i < 2; i++) {
                    const float bv = BTR
                        ? sB[(n0w + nf * 8 + g) * G_ASTR + kb + c + i * 4]
                        : sB[(kb + c + i * 4) * G_BSTR0 + n0w + nf * 8 + g];
                    split_tf32(bv, bhi[nf][i], blo[nf][i]);
                }
#pragma unroll
            for (int mf = 0; mf < 4; mf++) {
                uint32_t ahi[4], alo[4];
#pragma unroll
                for (int i = 0; i < 4; i++) {
                    const int r = m0w + mf * 16 + g + (i & 1) * 8;
                    const int cc = kb + c + (i >> 1) * 4;
                    split_tf32(sA[r * G_ASTR + cc], ahi[i], alo[i]);
                }
#pragma unroll
                for (int nf = 0; nf < 4; nf++) {
                    mma_tf32(acc[mf][nf], ahi, bhi[nf]);
                    mma_tf32(acc[mf][nf], alo, bhi[nf]);
                    mma_tf32(acc[mf][nf], ahi, blo[nf]);
                }
            }
        }
        __syncthreads();
    }

#pragma unroll
    for (int nf = 0; nf < 4; nf++) {
        const int col = n0 + n0w + nf * 8 + 2 * c;
        const float b0 = bias ? bias[col] : 0.f;
        const float b1 = bias ? bias[col + 1] : 0.f;
#pragma unroll
        for (int mf = 0; mf < 4; mf++) {
            const int r0 = m0 + m0w + mf * 16 + g;
            float2 v0 = make_float2(acc[mf][nf][0] + b0, acc[mf][nf][1] + b1);
            float2 v1 = make_float2(acc[mf][nf][2] + b0, acc[mf][nf][3] + b1);
            *reinterpret_cast<float2*>(Cm + (size_t)r0 * N + col) = v0;
            *reinterpret_cast<float2*>(Cm + (size_t)(r0 + 8) * N + col) = v1;
        }
    }
}

// =====================================================================
// Weight folding: W2 K/V sections = per-head Wk/Wv @ Wqkv block
// =====================================================================
__global__ __launch_bounds__(256)
void wfold_kernel(const float* __restrict__ Wqkv, const float* __restrict__ Wk,
                  const float* __restrict__ Wv, float* __restrict__ W2)
{
    __shared__ float sW[64 * 65];
    __shared__ float sQ[64 * 65];
    const int tid = threadIdx.x;
    const int tx = tid & 15, ty = tid >> 4;
    const int j0 = blockIdx.x * 64;
    const int sec = blockIdx.y;
    const int kv = sec >> 4, h = sec & 15;
    const float* Wsub = kv ? Wv : Wk;
    const size_t rowbase = (size_t)(C_ + kv * C_ + h * 64);

    for (int idx = tid; idx < 4096; idx += 256) {
        const int r = idx >> 6, cc = idx & 63;
        sW[r * 65 + cc] = Wsub[idx];
        sQ[r * 65 + cc] = Wqkv[(rowbase + r) * C_ + j0 + cc];
    }
    __syncthreads();

    float acc[4][4];
#pragma unroll
    for (int r = 0; r < 4; r++)
#pragma unroll
        for (int c = 0; c < 4; c++) acc[r][c] = 0.f;
#pragma unroll 8
    for (int e = 0; e < 64; e++) {
        float wf[4], qf[4];
#pragma unroll
        for (int r = 0; r < 4; r++) wf[r] = sW[(ty + 16*r) * 65 + e];
#pragma unroll
        for (int c = 0; c < 4; c++) qf[c] = sQ[e * 65 + tx + 16*c];
#pragma unroll
        for (int r = 0; r < 4; r++)
#pragma unroll
            for (int c = 0; c < 4; c++) acc[r][c] = fmaf(wf[r], qf[c], acc[r][c]);
    }
#pragma unroll
    for (int r = 0; r < 4; r++)
#pragma unroll
        for (int c = 0; c < 4; c++)
            W2[(rowbase + ty + 16*r) * C_ + j0 + tx + 16*c] = acc[r][c];
}

// copy Q section of Wqkv into W2 (rows 0..C)
__global__ void copyq_kernel(const float* __restrict__ Wqkv, float* __restrict__ W2)
{
    const size_t i = (size_t)blockIdx.x * 256 + threadIdx.x;
    reinterpret_cast<float4*>(W2)[i] = reinterpret_cast<const float4*>(Wqkv)[i];
}

// folded bias b2 (3C)
__global__ void b2fold_kernel(const float* __restrict__ bqkv, const float* __restrict__ Wk,
                              const float* __restrict__ bk, const float* __restrict__ Wv,
                              const float* __restrict__ bv, float* __restrict__ b2)
{
    const int i = blockIdx.x * 256 + threadIdx.x;
    if (i < C_) { b2[i] = bqkv[i]; return; }
    const int kv = (i - C_) / C_;
    const int d = (i - C_) - kv * C_;
    const int h = d >> 6, dd = d & 63;
    const float* W = kv ? Wv : Wk;
    const float* bb = kv ? bv : bk;
    float s = bb[dd];
    for (int e = 0; e < 64; e++)
        s = fmaf(W[dd * 64 + e], bqkv[C_ + kv * C_ + h * 64 + e], s);
    b2[i] = s;
}

// =====================================================================
// q_a[h] = agent_tokens[h] @ Wq^T + bq
// =====================================================================
__global__ __launch_bounds__(256)
void qa_kernel(const float* __restrict__ ag, const float* __restrict__ Wq,
               const float* __restrict__ bq, float* __restrict__ qa)
{
    __shared__ float sA[64 * 65];
    __shared__ float sW[64 * 65];
    const int tid = threadIdx.x;
    const int tx = tid & 15, ty = tid >> 4;
    const int h = blockIdx.x;

    for (int idx = tid; idx < 4096; idx += 256) {
        sA[(idx >> 6) * 65 + (idx & 63)] = ag[h * 4096 + idx];
        sW[(idx >> 6) * 65 + (idx & 63)] = Wq[idx];
    }
    __syncthreads();

    float acc[4][4];
#pragma unroll
    for (int r = 0; r < 4; r++)
#pragma unroll
        for (int c = 0; c < 4; c++) acc[r][c] = bq[tx + 16*c];
#pragma unroll 8
    for (int e = 0; e < 64; e++) {
        float af[4], wf[4];
#pragma unroll
        for (int r = 0; r < 4; r++) af[r] = sA[(ty + 16*r) * 65 + e];
#pragma unroll
        for (int c = 0; c < 4; c++) wf[c] = sW[(tx + 16*c) * 65 + e];
#pragma unroll
        for (int r = 0; r < 4; r++)
#pragma unroll
            for (int c = 0; c < 4; c++) acc[r][c] = fmaf(af[r], wf[c], acc[r][c]);
    }
#pragma unroll
    for (int r = 0; r < 4; r++)
#pragma unroll
        for (int c = 0; c < 4; c++)
            qa[h * 4096 + (ty + 16*r) * 64 + tx + 16*c] = acc[r][c];
}

// b' = Wproj @ bout + bproj
__global__ void bcomb_kernel(const float* __restrict__ Wproj, const float* __restrict__ bout,
                             const float* __restrict__ bproj, float* __restrict__ bcomb)
{
    const int i = blockIdx.x * 256 + threadIdx.x;
    float s = bproj[i];
    for (int k = 0; k < C_; k++) s = fmaf(Wproj[(size_t)i * C_ + k], bout[k], s);
    bcomb[i] = s;
}

// =====================================================================
// Stage 1 (lean): k_a/v_a pre-projected in qkv buffer.
// =====================================================================
constexpr int S1P = 65;
constexpr int S1_SMEM = 4 * 64 * S1P * (int)sizeof(float);   // 66560 B

__global__ __launch_bounds__(256)
void stage1_kernel(const float* __restrict__ qkv, const float* __restrict__ qa,
                   float* __restrict__ pm, float* __restrict__ pl,
                   float* __restrict__ pacc)
{
    extern __shared__ float sm1[];
    float* sQa = sm1;
    float* sK  = sQa + 64 * S1P;
    float* sV  = sK  + 64 * S1P;
    float* sP  = sV  + 64 * S1P;

    const int tid = threadIdx.x;
    const int tx = tid & 15, ty = tid >> 4;
    const int chunk = blockIdx.x, bh = blockIdx.y;
    const int b = bh >> 4, h = bh & 15;

    for (int idx = tid; idx < 4096; idx += 256)
        sQa[(idx >> 6) * S1P + (idx & 63)] = qa[h * 4096 + idx];

    float m_run[4], l_run[4], acc[4][4];
#pragma unroll
    for (int r = 0; r < 4; r++) {
        m_run[r] = -1e30f; l_run[r] = 0.f;
#pragma unroll
        for (int c = 0; c < 4; c++) acc[r][c] = 0.f;
    }

    const size_t rowbase = (size_t)(b * T_) * C3_;

    for (int kt = 0; kt < CT_ / KT_; kt++) {
        const int t0 = chunk * CT_ + kt * KT_;

        for (int idx = tid; idx < 1024; idx += 256) {
            const int row = idx >> 4, c4 = idx & 15;
            const size_t base = rowbase + (size_t)(t0 + row) * C3_ + h * 64 + c4 * 4;
            const float4 kv4 = *reinterpret_cast<const float4*>(qkv + base + C_);
            const float4 vv4 = *reinterpret_cast<const float4*>(qkv + base + 2 * C_);
            float* dk = &sK[row * S1P + c4 * 4];
            float* dv = &sV[row * S1P + c4 * 4];
            dk[0] = kv4.x; dk[1] = kv4.y; dk[2] = kv4.z; dk[3] = kv4.w;
            dv[0] = vv4.x; dv[1] = vv4.y; dv[2] = vv4.z; dv[3] = vv4.w;
        }
        __syncthreads();

        {
            float s[4][4];
#pragma unroll
            for (int r = 0; r < 4; r++)
#pragma unroll
                for (int c = 0; c < 4; c++) s[r][c] = 0.f;
#pragma unroll 8
            for (int e = 0; e < 64; e++) {
                float qf[4], kf[4];
#pragma unroll
                for (int r = 0; r < 4; r++) qf[r] = sQa[(ty + 16*r) * S1P + e];
#pragma unroll
                for (int c = 0; c < 4; c++) kf[c] = sK[(tx + 16*c) * S1P + e];
#pragma unroll
                for (int r = 0; r < 4; r++)
#pragma unroll
                    for (int c = 0; c < 4; c++) s[r][c] = fmaf(qf[r], kf[c], s[r][c]);
            }
#pragma unroll
            for (int r = 0; r < 4; r++) {
                float mt = -1e30f;
#pragma unroll
                for (int c = 0; c < 4; c++) { s[r][c] *= SCALE_; mt = fmaxf(mt, s[r][c]); }
#pragma unroll
                for (int ms = 8; ms >= 1; ms >>= 1)
                    mt = fmaxf(mt, __shfl_xor_sync(0xffffffffu, mt, ms));
                const float mn = fmaxf(m_run[r], mt);
                const float corr = __expf(m_run[r] - mn);
                float rs = 0.f;
#pragma unroll
                for (int c = 0; c < 4; c++) {
                    const float p = __expf(s[r][c] - mn);
                    sP[(ty + 16*r) * S1P + tx + 16*c] = p;
                    rs += p;
                }
#pragma unroll
                for (int ms = 8; ms >= 1; ms >>= 1)
                    rs += __shfl_xor_sync(0xffffffffu, rs, ms);
                l_run[r] = l_run[r] * corr + rs;
                m_run[r] = mn;
#pragma unroll
                for (int c = 0; c < 4; c++) acc[r][c] *= corr;
            }
        }
        __syncthreads();

#pragma unroll 8
        for (int t = 0; t < 64; t++) {
            float pf[4], vf[4];
#pragma unroll
            for (int r = 0; r < 4; r++) pf[r] = sP[(ty + 16*r) * S1P + t];
#pragma unroll
            for (int c = 0; c < 4; c++) vf[c] = sV[t * S1P + tx + 16*c];
#pragma unroll
            for (int r = 0; r < 4; r++)
#pragma unroll
                for (int c = 0; c < 4; c++) acc[r][c] = fmaf(pf[r], vf[c], acc[r][c]);
        }
        __syncthreads();
    }

    const int pi = bh * NCHUNK_ + chunk;
    if (tx == 0) {
#pragma unroll
        for (int r = 0; r < 4; r++) {
            pm[pi * 64 + ty + 16*r] = m_run[r];
            pl[pi * 64 + ty + 16*r] = l_run[r];
        }
    }
#pragma unroll
    for (int r = 0; r < 4; r++)
#pragma unroll
        for (int c = 0; c < 4; c++)
            pacc[(size_t)pi * 4096 + (ty + 16*r) * 64 + tx + 16*c] = acc[r][c];
}

// combine split-T partials -> c1[b,h,a,d]
__global__ __launch_bounds__(256)
void s1combine_kernel(const float* __restrict__ pm, const float* __restrict__ pl,
                      const float* __restrict__ pacc, float* __restrict__ c1)
{
    const int bh = blockIdx.x;
    const int tid = threadIdx.x;
    const int a = tid >> 2, dg = tid & 3;

    float mc[NCHUNK_], lc[NCHUNK_];
    float m = -1e30f;
#pragma unroll
    for (int c = 0; c < NCHUNK_; c++) {
        mc[c] = pm[(bh * NCHUNK_ + c) * 64 + a];
        lc[c] = pl[(bh * NCHUNK_ + c) * 64 + a];
        m = fmaxf(m, mc[c]);
    }
    float l = 0.f, w[NCHUNK_];
#pragma unroll
    for (int c = 0; c < NCHUNK_; c++) { w[c] = __expf(mc[c] - m); l += lc[c] * w[c]; }
    const float inv = 1.f / l;
#pragma unroll
    for (int j = 0; j < 16; j++) {
        const int d = dg * 16 + j;
        float s = 0.f;
#pragma unroll
        for (int c = 0; c < NCHUNK_; c++)
            s += pacc[(size_t)(bh * NCHUNK_ + c) * 4096 + a * 64 + d] * w[c];
        c1[bh * 4096 + a * 64 + d] = s * inv;
    }
}

// =====================================================================
// Stage 2: per (b,h, 128-token tile). Emits s2 + c2.
// =====================================================================
constexpr int S2P = 65;
constexpr int S2_SMEM = (64 + 128 + 128) * S2P * (int)sizeof(float);  // 83200 B

__global__ __launch_bounds__(256)
void stage2_kernel(const float* __restrict__ qkv, const float* __restrict__ c1,
                   float* __restrict__ s2out, float* __restrict__ c2)
{
    extern __shared__ float sm2[];
    float* sC1 = sm2;
    float* sQ  = sC1 + 64 * S2P;
    float* sP  = sQ + 128 * S2P;

    const int tid = threadIdx.x;
    const int tx = tid & 15, ty = tid >> 4;
    const int bh = blockIdx.y;
    const int b = bh >> 4, h = bh & 15;
    const int t0 = blockIdx.x * 128;

    for (int idx = tid; idx < 4096; idx += 256)
        sC1[(idx >> 6) * S2P + (idx & 63)] = c1[bh * 4096 + idx];
    for (int idx = tid; idx < 2048; idx += 256) {
        const int row = idx >> 4, c4 = idx & 15;
        const float4 v = *reinterpret_cast<const float4*>(
            qkv + (size_t)(b * T_ + t0 + row) * C3_ + h * 64 + c4 * 4);
        float* d = &sQ[row * S2P + c4 * 4];
        d[0] = v.x; d[1] = v.y; d[2] = v.z; d[3] = v.w;
    }
    __syncthreads();

    float s[8][4];
#pragma unroll
    for (int r = 0; r < 8; r++)
#pragma unroll
        for (int c = 0; c < 4; c++) s[r][c] = 0.f;
#pragma unroll 8
    for (int d = 0; d < 64; d++) {
        float qf[8], cf[4];
#pragma unroll
        for (int r = 0; r < 8; r++) qf[r] = sQ[(ty + 16*r) * S2P + d];
#pragma unroll
        for (int c = 0; c < 4; c++) cf[c] = sC1[(tx + 16*c) * S2P + d];
#pragma unroll
        for (int r = 0; r < 8; r++)
#pragma unroll
            for (int c = 0; c < 4; c++) s[r][c] = fmaf(qf[r], cf[c], s[r][c]);
    }

#pragma unroll
    for (int r = 0; r < 8; r++) {
        float mt = -1e30f;
#pragma unroll
        for (int c = 0; c < 4; c++) { s[r][c] *= SCALE_; mt = fmaxf(mt, s[r][c]); }
#pragma unroll
        for (int ms = 8; ms >= 1; ms >>= 1)
            mt = fmaxf(mt, __shfl_xor_sync(0xffffffffu, mt, ms));
        float rs = 0.f;
#pragma unroll
        for (int c = 0; c < 4; c++) { s[r][c] = __expf(s[r][c] - mt); rs += s[r][c]; }
#pragma unroll
        for (int ms = 8; ms >= 1; ms >>= 1)
            rs += __shfl_xor_sync(0xffffffffu, rs, ms);
        const float inv = 1.f / rs;
        const int t = t0 + ty + 16*r;
        const size_t so = ((size_t)bh * T_ + t) * 64;
#pragma unroll
        for (int c = 0; c < 4; c++) {
            const float p = s[r][c] * inv;
            sP[(ty + 16*r) * S2P + tx + 16*c] = p;
            s2out[so + tx + 16*c] = p;
        }
    }
    __syncthreads();

    float acc[8][4];
#pragma unroll
    for (int r = 0; r < 8; r++)
#pragma unroll
        for (int c = 0; c < 4; c++) acc[r][c] = 0.f;
#pragma unroll 8
    for (int a = 0; a < 64; a++) {
        float pf[8], cf[4];
#pragma unroll
        for (int r = 0; r < 8; r++) pf[r] = sP[(ty + 16*r) * S2P + a];
#pragma unroll
        for (int c = 0; c < 4; c++) cf[c] = sC1[a * S2P + tx + 16*c];
#pragma unroll
        for (int r = 0; r < 8; r++)
#pragma unroll
            for (int c = 0; c < 4; c++) acc[r][c] = fmaf(pf[r], cf[c], acc[r][c]);
    }
#pragma unroll
    for (int r = 0; r < 8; r++) {
        const int t = t0 + ty + 16*r;
#pragma unroll
        for (int c = 0; c < 4; c++)
            c2[(size_t)(b * T_ + t) * C_ + h * 64 + tx + 16*c] = acc[r][c];
    }
}

// =====================================================================
// launch
// =====================================================================
extern "C" void kernel_launch(void* const* d_in, const int* in_sizes, int n_in,
                              void* d_out, int out_size)
{
    (void)in_sizes; (void)n_in; (void)out_size;
    const float* x     = (const float*)d_in[0];
    const float* Wqkv  = (const float*)d_in[1];
    const float* bqkv  = (const float*)d_in[2];
    const float* Wq    = (const float*)d_in[3];
    const float* bq    = (const float*)d_in[4];
    const float* Wk    = (const float*)d_in[5];
    const float* bk    = (const float*)d_in[6];
    const float* Wv    = (const float*)d_in[7];
    const float* bv    = (const float*)d_in[8];
    const float* ag    = (const float*)d_in[9];
    const float* Wout  = (const float*)d_in[10];
    const float* bout  = (const float*)d_in[11];
    const float* Wproj = (const float*)d_in[12];
    const float* bproj = (const float*)d_in[13];
    float* out = (float*)d_out;

    float *qkv, *w2, *b2, *qa, *pm, *pl, *pacc, *c1, *c2, *wcomb, *bcomb;
    cudaGetSymbolAddress((void**)&qkv,   g_qkv);
    cudaGetSymbolAddress((void**)&w2,    g_w2);
    cudaGetSymbolAddress((void**)&b2,    g_b2);
    cudaGetSymbolAddress((void**)&qa,    g_qa);
    cudaGetSymbolAddress((void**)&pm,    g_pm);
    cudaGetSymbolAddress((void**)&pl,    g_pl);
    cudaGetSymbolAddress((void**)&pacc,  g_pacc);
    cudaGetSymbolAddress((void**)&c1,    g_c1);
    cudaGetSymbolAddress((void**)&c2,    g_c2);
    cudaGetSymbolAddress((void**)&wcomb, g_wcomb);
    cudaGetSymbolAddress((void**)&bcomb, g_bcomb);

    cudaFuncSetAttribute(gemm_tf32_kernel<1>, cudaFuncAttributeMaxDynamicSharedMemorySize, G_SMEM);
    cudaFuncSetAttribute(gemm_tf32_kernel<0>, cudaFuncAttributeMaxDynamicSharedMemorySize, G_SMEM);
    cudaFuncSetAttribute(stage1_kernel, cudaFuncAttributeMaxDynamicSharedMemorySize, S1_SMEM);
    cudaFuncSetAttribute(stage2_kernel, cudaFuncAttributeMaxDynamicSharedMemorySize, S2_SMEM);

    // 0. fold per-head Wk/Wv into Wqkv  (W2, b2)
    copyq_kernel<<<C_ * C_ / (256 * 4), 256>>>(Wqkv, w2);
    wfold_kernel<<<dim3(C_/64, 2*NH_), 256>>>(Wqkv, Wk, Wv, w2);
    b2fold_kernel<<<C3_/256, 256>>>(bqkv, Wk, bk, Wv, bv, b2);
    // 1. qkv = x @ W2^T + b2  ->  [q | k_a | v_a]
    gemm_tf32_kernel<1><<<dim3(C3_/128, BT_/128), 256, G_SMEM>>>(x, w2, b2, qkv, BT_, C3_, C_);
    // 2. q_a (per-head), combined bias, combined weight wcomb = Wproj @ Wout
    qa_kernel<<<NH_, 256>>>(ag, Wq, bq, qa);
    bcomb_kernel<<<C_/256, 256>>>(Wproj, bout, bproj, bcomb);
    gemm_tf32_kernel<0><<<dim3(C_/128, C_/128), 256, G_SMEM>>>(Wproj, Wout, nullptr, wcomb, C_, C_, C_);
    // 3. stage-1 attention (pre-projected k_a/v_a, split-T online softmax)
    stage1_kernel<<<dim3(NCHUNK_, BH_), 256, S1_SMEM>>>(qkv, qa, pm, pl, pacc);
    s1combine_kernel<<<BH_, 256>>>(pm, pl, pacc, c1);
    // 4. stage-2 attention -> s2 (output #2) + c2
    stage2_kernel<<<dim3(T_/128, BH_), 256, S2_SMEM>>>(qkv, c1, out + (size_t)BT_ * C_, c2);
    // 5. y = c2 @ (Wproj@Wout)^T + b'  -> output #1
    gemm_tf32_kernel<1><<<dim3(C_/128, BT_/128), 256, G_SMEM>>>(c2, wcomb, bcomb, out, BT_, C_, C_);
}

// round 15
// speedup vs baseline: 1.2406x; 1.0478x over previous
#include <cuda_runtime.h>
#include <cstdint>

// ---------------- problem constants ----------------
constexpr int B_  = 4;
constexpr int T_  = 4096;
constexpr int C_  = 1024;
constexpr int NH_ = 16;
constexpr int HD_ = 64;
constexpr int A_  = 64;
constexpr int C3_ = 3 * C_;          // 3072
constexpr int BT_ = B_ * T_;         // 16384 rows
constexpr int BH_ = B_ * NH_;        // 64 (b,h) pairs
constexpr int NCHUNK_ = 8;           // T split for stage-1
constexpr int CT_ = T_ / NCHUNK_;    // 512 keys per chunk
constexpr int KT_ = 64;              // key tile
constexpr float SCALE_ = 0.125f;     // 1/sqrt(64)

// ---------------- scratch (device globals: no cudaMalloc allowed) ----------------
__device__ float g_qkv[(size_t)BT_ * C3_];                    // [B*T, 3C] = q | k_a | v_a
__device__ float g_w2[(size_t)C3_ * C_];                      // folded Wqkv (fp32)
__device__ float g_b2[C3_];                                   // folded bqkv
__device__ float g_xs[2 * (size_t)BT_ * C_];                  // x split: hi | lo planes
__device__ float g_c2s[2 * (size_t)BT_ * C_];                 // c2 split: hi | lo planes
__device__ float g_qa[NH_ * A_ * HD_];                        // q_a (batch-independent)
__device__ float g_pm[BH_ * NCHUNK_ * A_];                    // stage-1 partial max
__device__ float g_pl[BH_ * NCHUNK_ * A_];                    // stage-1 partial sum
__device__ float g_pacc[(size_t)BH_ * NCHUNK_ * A_ * HD_];    // stage-1 partial acc
__device__ float g_c1[BH_ * A_ * HD_];                        // agent context
__device__ float g_wcomb[C_ * C_];                            // Wproj @ Wout
__device__ float g_bcomb[C_];                                 // Wproj @ bout + bproj

// =====================================================================
// TF32 tensor-core helpers
// =====================================================================
__device__ __forceinline__ void split_tf32(float x, uint32_t& hi, uint32_t& lo) {
    uint32_t h;
    asm("cvt.rna.tf32.f32 %0, %1;" : "=r"(h) : "f"(x));
    float r = x - __uint_as_float(h);     // exact (hi = x rounded to 11 bits)
    uint32_t l;
    asm("cvt.rna.tf32.f32 %0, %1;" : "=r"(l) : "f"(r));
    hi = h; lo = l;
}

__device__ __forceinline__ void mma_tf32(float c[4], const uint32_t a[4], const uint32_t b[2]) {
    asm volatile(
        "mma.sync.aligned.m16n8k8.row.col.f32.tf32.tf32.f32 "
        "{%0,%1,%2,%3}, {%4,%5,%6,%7}, {%8,%9}, {%0,%1,%2,%3};"
        : "+f"(c[0]), "+f"(c[1]), "+f"(c[2]), "+f"(c[3])
        : "r"(a[0]), "r"(a[1]), "r"(a[2]), "r"(a[3]), "r"(b[0]), "r"(b[1]));
}

__device__ __forceinline__ void cp_async16(uint32_t saddr, const void* gaddr) {
    asm volatile("cp.async.cg.shared.global [%0], [%1], 16;" :: "r"(saddr), "l"(gaddr));
}

// element-wise hi/lo split:  in[n] -> hi plane, lo plane  (float4 per thread)
__global__ void split_kernel(const float* __restrict__ in, float* __restrict__ hi,
                             float* __restrict__ lo)
{
    const size_t i = ((size_t)blockIdx.x * 256 + threadIdx.x) * 4;
    const float4 v = *reinterpret_cast<const float4*>(in + i);
    uint32_t h0, l0, h1, l1, h2, l2, h3, l3;
    split_tf32(v.x, h0, l0); split_tf32(v.y, h1, l1);
    split_tf32(v.z, h2, l2); split_tf32(v.w, h3, l3);
    float4 hv = make_float4(__uint_as_float(h0), __uint_as_float(h1),
                            __uint_as_float(h2), __uint_as_float(h3));
    float4 lv = make_float4(__uint_as_float(l0), __uint_as_float(l1),
                            __uint_as_float(l2), __uint_as_float(l3));
    *reinterpret_cast<float4*>(hi + i) = hv;
    *reinterpret_cast<float4*>(lo + i) = lv;
}

// =====================================================================
// A-pre-split TF32 GEMM:  C[M,N] = A[M,K] @ B^T + bias
// A arrives as tf32 hi/lo planes; B [N,K] fp32, split in-loop (8 elem/k8 only).
// BM=BN=128, BK=32, 256 threads (8 warps, 2x4), warp tile 64x32.
// Stage = Ahi + Alo + B = 3 x 4608 floats; 110.6KB smem, 2 CTAs/SM.
// =====================================================================
constexpr int AS_STR = 36;
constexpr int AS_TILE = 128 * AS_STR;            // 4608 floats
constexpr int AS_STAGE = 3 * AS_TILE;            // 13824 floats
constexpr int AS_SMEM = 2 * AS_STAGE * (int)sizeof(float);   // 110592 B

__device__ __forceinline__ void as_load_tile(const float* __restrict__ Ahi,
                                             const float* __restrict__ Alo,
                                             const float* __restrict__ Bm,
                                             float* st, int K,
                                             int m0, int n0, int k0, int tid)
{
    float* sAh = st;
    float* sAl = st + AS_TILE;
    float* sB  = st + 2 * AS_TILE;
#pragma unroll
    for (int q = 0; q < 4; q++) {
        const int chunk = tid + q * 256;
        const int row = chunk >> 3, c16 = chunk & 7;
        const int so = row * AS_STR + c16 * 4;
        const size_t goA = (size_t)(m0 + row) * K + k0 + c16 * 4;
        const size_t goB = (size_t)(n0 + row) * K + k0 + c16 * 4;
        cp_async16((uint32_t)__cvta_generic_to_shared(sAh + so), Ahi + goA);
        cp_async16((uint32_t)__cvta_generic_to_shared(sAl + so), Alo + goA);
        cp_async16((uint32_t)__cvta_generic_to_shared(sB + so),  Bm + goB);
    }
}

__global__ __launch_bounds__(256, 2)
void gemm_as_kernel(const float* __restrict__ Ahi, const float* __restrict__ Alo,
                    const float* __restrict__ Bm, const float* __restrict__ bias,
                    float* __restrict__ Cm, int M, int N, int K)
{
    extern __shared__ float asm_[];
    const int tid = threadIdx.x;
    const int warp = tid >> 5, lane = tid & 31;
    const int g = lane >> 2, c = lane & 3;
    const int m0w = (warp >> 2) * 64;
    const int n0w = (warp & 3) * 32;
    const int m0 = blockIdx.y * 128, n0 = blockIdx.x * 128;

    float acc[4][4][4];
#pragma unroll
    for (int mf = 0; mf < 4; mf++)
#pragma unroll
        for (int nf = 0; nf < 4; nf++)
#pragma unroll
            for (int i = 0; i < 4; i++) acc[mf][nf][i] = 0.f;

    const int nk = K >> 5;

    as_load_tile(Ahi, Alo, Bm, asm_, K, m0, n0, 0, tid);
    asm volatile("cp.async.commit_group;");

    for (int kt = 0; kt < nk; kt++) {
        float* st = asm_ + (kt & 1) * AS_STAGE;
        const uint32_t* sAh = reinterpret_cast<const uint32_t*>(st);
        const uint32_t* sAl = sAh + AS_TILE;
        const float* sB = st + 2 * AS_TILE;
        if (kt + 1 < nk) {
            as_load_tile(Ahi, Alo, Bm, asm_ + ((kt + 1) & 1) * AS_STAGE,
                         K, m0, n0, (kt + 1) * 32, tid);
            asm volatile("cp.async.commit_group;");
            asm volatile("cp.async.wait_group 1;");
        } else {
            asm volatile("cp.async.wait_group 0;");
        }
        __syncthreads();

#pragma unroll
        for (int ks = 0; ks < 4; ks++) {
            const int kb = ks * 8;
            uint32_t bhi[4][2], blo[4][2];
#pragma unroll
            for (int nf = 0; nf < 4; nf++)
#pragma unroll
                for (int i = 0; i < 2; i++) {
                    const float bv = sB[(n0w + nf * 8 + g) * AS_STR + kb + c + i * 4];
                    split_tf32(bv, bhi[nf][i], blo[nf][i]);
                }
#pragma unroll
            for (int mf = 0; mf < 4; mf++) {
                uint32_t ahi[4], alo[4];
#pragma unroll
                for (int i = 0; i < 4; i++) {
                    const int idx = (m0w + mf * 16 + g + (i & 1) * 8) * AS_STR
                                  + kb + c + (i >> 1) * 4;
                    ahi[i] = sAh[idx];
                    alo[i] = sAl[idx];
                }
#pragma unroll
                for (int nf = 0; nf < 4; nf++) {
                    mma_tf32(acc[mf][nf], ahi, bhi[nf]);
                    mma_tf32(acc[mf][nf], alo, bhi[nf]);
                    mma_tf32(acc[mf][nf], ahi, blo[nf]);
                }
            }
        }
        __syncthreads();
    }

#pragma unroll
    for (int nf = 0; nf < 4; nf++) {
        const int col = n0 + n0w + nf * 8 + 2 * c;
        const float b0 = bias ? bias[col] : 0.f;
        const float b1 = bias ? bias[col + 1] : 0.f;
#pragma unroll
        for (int mf = 0; mf < 4; mf++) {
            const int r0 = m0 + m0w + mf * 16 + g;
            float2 v0 = make_float2(acc[mf][nf][0] + b0, acc[mf][nf][1] + b1);
            float2 v1 = make_float2(acc[mf][nf][2] + b0, acc[mf][nf][3] + b1);
            *reinterpret_cast<float2*>(Cm + (size_t)r0 * N + col) = v0;
            *reinterpret_cast<float2*>(Cm + (size_t)(r0 + 8) * N + col) = v1;
        }
    }
}

// =====================================================================
// In-loop-split TF32 GEMM, BTR=0 (C = A @ B) — used only for small wcomb.
// =====================================================================
constexpr int G_ASTR = 36;
constexpr int G_BSTR0 = 136;
constexpr int G_ATILE = 128 * G_ASTR;
constexpr int G_STAGE = G_ATILE * 2;
constexpr int G_SMEM = 2 * G_STAGE * (int)sizeof(float);   // 73728 B

__device__ __forceinline__ void g_load_tile0(const float* __restrict__ A,
                                             const float* __restrict__ Bm,
                                             float* sA, float* sB,
                                             int N, int K, int m0, int n0, int k0, int tid)
{
#pragma unroll
    for (int q = 0; q < 4; q++) {
        const int chunk = tid + q * 256;
        const int row = chunk >> 3, c16 = chunk & 7;
        cp_async16((uint32_t)__cvta_generic_to_shared(sA + row * G_ASTR + c16 * 4),
                   A + (size_t)(m0 + row) * K + k0 + c16 * 4);
    }
#pragma unroll
    for (int q = 0; q < 4; q++) {
        const int chunk = tid + q * 256;
        const int row = chunk >> 5, c16 = chunk & 31;
        cp_async16((uint32_t)__cvta_generic_to_shared(sB + row * G_BSTR0 + c16 * 4),
                   Bm + (size_t)(k0 + row) * N + n0 + c16 * 4);
    }
}

__global__ __launch_bounds__(256, 2)
void gemm_tf32_nn_kernel(const float* __restrict__ A, const float* __restrict__ Bm,
                         float* __restrict__ Cm, int M, int N, int K)
{
    extern __shared__ float gsm[];
    const int tid = threadIdx.x;
    const int warp = tid >> 5, lane = tid & 31;
    const int g = lane >> 2, c = lane & 3;
    const int m0w = (warp >> 2) * 64;
    const int n0w = (warp & 3) * 32;
    const int m0 = blockIdx.y * 128, n0 = blockIdx.x * 128;

    float acc[4][4][4];
#pragma unroll
    for (int mf = 0; mf < 4; mf++)
#pragma unroll
        for (int nf = 0; nf < 4; nf++)
#pragma unroll
            for (int i = 0; i < 4; i++) acc[mf][nf][i] = 0.f;

    const int nk = K >> 5;
    g_load_tile0(A, Bm, gsm, gsm + G_ATILE, N, K, m0, n0, 0, tid);
    asm volatile("cp.async.commit_group;");

    for (int kt = 0; kt < nk; kt++) {
        float* sA = gsm + (kt & 1) * G_STAGE;
        float* sB = sA + G_ATILE;
        if (kt + 1 < nk) {
            float* sAn = gsm + ((kt + 1) & 1) * G_STAGE;
            g_load_tile0(A, Bm, sAn, sAn + G_ATILE, N, K, m0, n0, (kt + 1) * 32, tid);
            asm volatile("cp.async.commit_group;");
            asm volatile("cp.async.wait_group 1;");
        } else {
            asm volatile("cp.async.wait_group 0;");
        }
        __syncthreads();

#pragma unroll
        for (int ks = 0; ks < 4; ks++) {
            const int kb = ks * 8;
            uint32_t bhi[4][2], blo[4][2];
#pragma unroll
            for (int nf = 0; nf < 4; nf++)
#pragma unroll
                for (int i = 0; i < 2; i++) {
                    const float bv = sB[(kb + c + i * 4) * G_BSTR0 + n0w + nf * 8 + g];
                    split_tf32(bv, bhi[nf][i], blo[nf][i]);
                }
#pragma unroll
            for (int mf = 0; mf < 4; mf++) {
                uint32_t ahi[4], alo[4];
#pragma unroll
                for (int i = 0; i < 4; i++) {
                    const int r = m0w + mf * 16 + g + (i & 1) * 8;
                    const int cc = kb + c + (i >> 1) * 4;
                    split_tf32(sA[r * G_ASTR + cc], ahi[i], alo[i]);
                }
#pragma unroll
                for (int nf = 0; nf < 4; nf++) {
                    mma_tf32(acc[mf][nf], ahi, bhi[nf]);
                    mma_tf32(acc[mf][nf], alo, bhi[nf]);
                    mma_tf32(acc[mf][nf], ahi, blo[nf]);
                }
            }
        }
        __syncthreads();
    }

#pragma unroll
    for (int nf = 0; nf < 4; nf++) {
        const int col = n0 + n0w + nf * 8 + 2 * c;
#pragma unroll
        for (int mf = 0; mf < 4; mf++) {
            const int r0 = m0 + m0w + mf * 16 + g;
            float2 v0 = make_float2(acc[mf][nf][0], acc[mf][nf][1]);
            float2 v1 = make_float2(acc[mf][nf][2], acc[mf][nf][3]);
            *reinterpret_cast<float2*>(Cm + (size_t)r0 * N + col) = v0;
            *reinterpret_cast<float2*>(Cm + (size_t)(r0 + 8) * N + col) = v1;
        }
    }
}

// =====================================================================
// Weight folding: W2 K/V sections = per-head Wk/Wv @ Wqkv block
// =====================================================================
__global__ __launch_bounds__(256)
void wfold_kernel(const float* __restrict__ Wqkv, const float* __restrict__ Wk,
                  const float* __restrict__ Wv, float* __restrict__ W2)
{
    __shared__ float sW[64 * 65];
    __shared__ float sQ[64 * 65];
    const int tid = threadIdx.x;
    const int tx = tid & 15, ty = tid >> 4;
    const int j0 = blockIdx.x * 64;
    const int sec = blockIdx.y;
    const int kv = sec >> 4, h = sec & 15;
    const float* Wsub = kv ? Wv : Wk;
    const size_t rowbase = (size_t)(C_ + kv * C_ + h * 64);

    for (int idx = tid; idx < 4096; idx += 256) {
        const int r = idx >> 6, cc = idx & 63;
        sW[r * 65 + cc] = Wsub[idx];
        sQ[r * 65 + cc] = Wqkv[(rowbase + r) * C_ + j0 + cc];
    }
    __syncthreads();

    float acc[4][4];
#pragma unroll
    for (int r = 0; r < 4; r++)
#pragma unroll
        for (int c = 0; c < 4; c++) acc[r][c] = 0.f;
#pragma unroll 8
    for (int e = 0; e < 64; e++) {
        float wf[4], qf[4];
#pragma unroll
        for (int r = 0; r < 4; r++) wf[r] = sW[(ty + 16*r) * 65 + e];
#pragma unroll
        for (int c = 0; c < 4; c++) qf[c] = sQ[e * 65 + tx + 16*c];
#pragma unroll
        for (int r = 0; r < 4; r++)
#pragma unroll
            for (int c = 0; c < 4; c++) acc[r][c] = fmaf(wf[r], qf[c], acc[r][c]);
    }
#pragma unroll
    for (int r = 0; r < 4; r++)
#pragma unroll
        for (int c = 0; c < 4; c++)
            W2[(rowbase + ty + 16*r) * C_ + j0 + tx + 16*c] = acc[r][c];
}

// copy Q section of Wqkv into W2 (rows 0..C)
__global__ void copyq_kernel(const float* __restrict__ Wqkv, float* __restrict__ W2)
{
    const size_t i = (size_t)blockIdx.x * 256 + threadIdx.x;
    reinterpret_cast<float4*>(W2)[i] = reinterpret_cast<const float4*>(Wqkv)[i];
}

// folded bias b2 (3C)
__global__ void b2fold_kernel(const float* __restrict__ bqkv, const float* __restrict__ Wk,
                              const float* __restrict__ bk, const float* __restrict__ Wv,
                              const float* __restrict__ bv, float* __restrict__ b2)
{
    const int i = blockIdx.x * 256 + threadIdx.x;
    if (i < C_) { b2[i] = bqkv[i]; return; }
    const int kv = (i - C_) / C_;
    const int d = (i - C_) - kv * C_;
    const int h = d >> 6, dd = d & 63;
    const float* W = kv ? Wv : Wk;
    const float* bb = kv ? bv : bk;
    float s = bb[dd];
    for (int e = 0; e < 64; e++)
        s = fmaf(W[dd * 64 + e], bqkv[C_ + kv * C_ + h * 64 + e], s);
    b2[i] = s;
}

// =====================================================================
// q_a[h] = agent_tokens[h] @ Wq^T + bq
// =====================================================================
__global__ __launch_bounds__(256)
void qa_kernel(const float* __restrict__ ag, const float* __restrict__ Wq,
               const float* __restrict__ bq, float* __restrict__ qa)
{
    __shared__ float sA[64 * 65];
    __shared__ float sW[64 * 65];
    const int tid = threadIdx.x;
    const int tx = tid & 15, ty = tid >> 4;
    const int h = blockIdx.x;

    for (int idx = tid; idx < 4096; idx += 256) {
        sA[(idx >> 6) * 65 + (idx & 63)] = ag[h * 4096 + idx];
        sW[(idx >> 6) * 65 + (idx & 63)] = Wq[idx];
    }
    __syncthreads();

    float acc[4][4];
#pragma unroll
    for (int r = 0; r < 4; r++)
#pragma unroll
        for (int c = 0; c < 4; c++) acc[r][c] = bq[tx + 16*c];
#pragma unroll 8
    for (int e = 0; e < 64; e++) {
        float af[4], wf[4];
#pragma unroll
        for (int r = 0; r < 4; r++) af[r] = sA[(ty + 16*r) * 65 + e];
#pragma unroll
        for (int c = 0; c < 4; c++) wf[c] = sW[(tx + 16*c) * 65 + e];
#pragma unroll
        for (int r = 0; r < 4; r++)
#pragma unroll
            for (int c = 0; c < 4; c++) acc[r][c] = fmaf(af[r], wf[c], acc[r][c]);
    }
#pragma unroll
    for (int r = 0; r < 4; r++)
#pragma unroll
        for (int c = 0; c < 4; c++)
            qa[h * 4096 + (ty + 16*r) * 64 + tx + 16*c] = acc[r][c];
}

// b' = Wproj @ bout + bproj
__global__ void bcomb_kernel(const float* __restrict__ Wproj, const float* __restrict__ bout,
                             const float* __restrict__ bproj, float* __restrict__ bcomb)
{
    const int i = blockIdx.x * 256 + threadIdx.x;
    float s = bproj[i];
    for (int k = 0; k < C_; k++) s = fmaf(Wproj[(size_t)i * C_ + k], bout[k], s);
    bcomb[i] = s;
}

// =====================================================================
// Stage 1 (lean): k_a/v_a pre-projected in qkv buffer.
// =====================================================================
constexpr int S1P = 65;
constexpr int S1_SMEM = 4 * 64 * S1P * (int)sizeof(float);   // 66560 B

__global__ __launch_bounds__(256)
void stage1_kernel(const float* __restrict__ qkv, const float* __restrict__ qa,
                   float* __restrict__ pm, float* __restrict__ pl,
                   float* __restrict__ pacc)
{
    extern __shared__ float sm1[];
    float* sQa = sm1;
    float* sK  = sQa + 64 * S1P;
    float* sV  = sK  + 64 * S1P;
    float* sP  = sV  + 64 * S1P;

    const int tid = threadIdx.x;
    const int tx = tid & 15, ty = tid >> 4;
    const int chunk = blockIdx.x, bh = blockIdx.y;
    const int b = bh >> 4, h = bh & 15;

    for (int idx = tid; idx < 4096; idx += 256)
        sQa[(idx >> 6) * S1P + (idx & 63)] = qa[h * 4096 + idx];

    float m_run[4], l_run[4], acc[4][4];
#pragma unroll
    for (int r = 0; r < 4; r++) {
        m_run[r] = -1e30f; l_run[r] = 0.f;
#pragma unroll
        for (int c = 0; c < 4; c++) acc[r][c] = 0.f;
    }

    const size_t rowbase = (size_t)(b * T_) * C3_;

    for (int kt = 0; kt < CT_ / KT_; kt++) {
        const int t0 = chunk * CT_ + kt * KT_;

        for (int idx = tid; idx < 1024; idx += 256) {
            const int row = idx >> 4, c4 = idx & 15;
            const size_t base = rowbase + (size_t)(t0 + row) * C3_ + h * 64 + c4 * 4;
            const float4 kv4 = *reinterpret_cast<const float4*>(qkv + base + C_);
            const float4 vv4 = *reinterpret_cast<const float4*>(qkv + base + 2 * C_);
            float* dk = &sK[row * S1P + c4 * 4];
            float* dv = &sV[row * S1P + c4 * 4];
            dk[0] = kv4.x; dk[1] = kv4.y; dk[2] = kv4.z; dk[3] = kv4.w;
            dv[0] = vv4.x; dv[1] = vv4.y; dv[2] = vv4.z; dv[3] = vv4.w;
        }
        __syncthreads();

        {
            float s[4][4];
#pragma unroll
            for (int r = 0; r < 4; r++)
#pragma unroll
                for (int c = 0; c < 4; c++) s[r][c] = 0.f;
#pragma unroll 8
            for (int e = 0; e < 64; e++) {
                float qf[4], kf[4];
#pragma unroll
                for (int r = 0; r < 4; r++) qf[r] = sQa[(ty + 16*r) * S1P + e];
#pragma unroll
                for (int c = 0; c < 4; c++) kf[c] = sK[(tx + 16*c) * S1P + e];
#pragma unroll
                for (int r = 0; r < 4; r++)
#pragma unroll
                    for (int c = 0; c < 4; c++) s[r][c] = fmaf(qf[r], kf[c], s[r][c]);
            }
#pragma unroll
            for (int r = 0; r < 4; r++) {
                float mt = -1e30f;
#pragma unroll
                for (int c = 0; c < 4; c++) { s[r][c] *= SCALE_; mt = fmaxf(mt, s[r][c]); }
#pragma unroll
                for (int ms = 8; ms >= 1; ms >>= 1)
                    mt = fmaxf(mt, __shfl_xor_sync(0xffffffffu, mt, ms));
                const float mn = fmaxf(m_run[r], mt);
                const float corr = __expf(m_run[r] - mn);
                float rs = 0.f;
#pragma unroll
                for (int c = 0; c < 4; c++) {
                    const float p = __expf(s[r][c] - mn);
                    sP[(ty + 16*r) * S1P + tx + 16*c] = p;
                    rs += p;
                }
#pragma unroll
                for (int ms = 8; ms >= 1; ms >>= 1)
                    rs += __shfl_xor_sync(0xffffffffu, rs, ms);
                l_run[r] = l_run[r] * corr + rs;
                m_run[r] = mn;
#pragma unroll
                for (int c = 0; c < 4; c++) acc[r][c] *= corr;
            }
        }
        __syncthreads();

#pragma unroll 8
        for (int t = 0; t < 64; t++) {
            float pf[4], vf[4];
#pragma unroll
            for (int r = 0; r < 4; r++) pf[r] = sP[(ty + 16*r) * S1P + t];
#pragma unroll
            for (int c = 0; c < 4; c++) vf[c] = sV[t * S1P + tx + 16*c];
#pragma unroll
            for (int r = 0; r < 4; r++)
#pragma unroll
                for (int c = 0; c < 4; c++) acc[r][c] = fmaf(pf[r], vf[c], acc[r][c]);
        }
        __syncthreads();
    }

    const int pi = bh * NCHUNK_ + chunk;
    if (tx == 0) {
#pragma unroll
        for (int r = 0; r < 4; r++) {
            pm[pi * 64 + ty + 16*r] = m_run[r];
            pl[pi * 64 + ty + 16*r] = l_run[r];
        }
    }
#pragma unroll
    for (int r = 0; r < 4; r++)
#pragma unroll
        for (int c = 0; c < 4; c++)
            pacc[(size_t)pi * 4096 + (ty + 16*r) * 64 + tx + 16*c] = acc[r][c];
}

// combine split-T partials -> c1[b,h,a,d]
__global__ __launch_bounds__(256)
void s1combine_kernel(const float* __restrict__ pm, const float* __restrict__ pl,
                      const float* __restrict__ pacc, float* __restrict__ c1)
{
    const int bh = blockIdx.x;
    const int tid = threadIdx.x;
    const int a = tid >> 2, dg = tid & 3;

    float mc[NCHUNK_], lc[NCHUNK_];
    float m = -1e30f;
#pragma unroll
    for (int c = 0; c < NCHUNK_; c++) {
        mc[c] = pm[(bh * NCHUNK_ + c) * 64 + a];
        lc[c] = pl[(bh * NCHUNK_ + c) * 64 + a];
        m = fmaxf(m, mc[c]);
    }
    float l = 0.f, w[NCHUNK_];
#pragma unroll
    for (int c = 0; c < NCHUNK_; c++) { w[c] = __expf(mc[c] - m); l += lc[c] * w[c]; }
    const float inv = 1.f / l;
#pragma unroll
    for (int j = 0; j < 16; j++) {
        const int d = dg * 16 + j;
        float s = 0.f;
#pragma unroll
        for (int c = 0; c < NCHUNK_; c++)
            s += pacc[(size_t)(bh * NCHUNK_ + c) * 4096 + a * 64 + d] * w[c];
        c1[bh * 4096 + a * 64 + d] = s * inv;
    }
}

// =====================================================================
// Stage 2: per (b,h, 128-token tile). Emits s2 + c2 in hi/lo split form
// (c2 feeds the A-pre-split final GEMM directly).
// =====================================================================
constexpr int S2P = 65;
constexpr int S2_SMEM = (64 + 128 + 128) * S2P * (int)sizeof(float);  // 83200 B

__global__ __launch_bounds__(256)
void stage2_kernel(const float* __restrict__ qkv, const float* __restrict__ c1,
                   float* __restrict__ s2out, float* __restrict__ c2hi,
                   float* __restrict__ c2lo)
{
    extern __shared__ float sm2[];
    float* sC1 = sm2;
    float* sQ  = sC1 + 64 * S2P;
    float* sP  = sQ + 128 * S2P;

    const int tid = threadIdx.x;
    const int tx = tid & 15, ty = tid >> 4;
    const int bh = blockIdx.y;
    const int b = bh >> 4, h = bh & 15;
    const int t0 = blockIdx.x * 128;

    for (int idx = tid; idx < 4096; idx += 256)
        sC1[(idx >> 6) * S2P + (idx & 63)] = c1[bh * 4096 + idx];
    for (int idx = tid; idx < 2048; idx += 256) {
        const int row = idx >> 4, c4 = idx & 15;
        const float4 v = *reinterpret_cast<const float4*>(
            qkv + (size_t)(b * T_ + t0 + row) * C3_ + h * 64 + c4 * 4);
        float* d = &sQ[row * S2P + c4 * 4];
        d[0] = v.x; d[1] = v.y; d[2] = v.z; d[3] = v.w;
    }
    __syncthreads();

    float s[8][4];
#pragma unroll
    for (int r = 0; r < 8; r++)
#pragma unroll
        for (int c = 0; c < 4; c++) s[r][c] = 0.f;
#pragma unroll 8
    for (int d = 0; d < 64; d++) {
        float qf[8], cf[4];
#pragma unroll
        for (int r = 0; r < 8; r++) qf[r] = sQ[(ty + 16*r) * S2P + d];
#pragma unroll
        for (int c = 0; c < 4; c++) cf[c] = sC1[(tx + 16*c) * S2P + d];
#pragma unroll
        for (int r = 0; r < 8; r++)
#pragma unroll
            for (int c = 0; c < 4; c++) s[r][c] = fmaf(qf[r], cf[c], s[r][c]);
    }

#pragma unroll
    for (int r = 0; r < 8; r++) {
        float mt = -1e30f;
#pragma unroll
        for (int c = 0; c < 4; c++) { s[r][c] *= SCALE_; mt = fmaxf(mt, s[r][c]); }
#pragma unroll
        for (int ms = 8; ms >= 1; ms >>= 1)
            mt = fmaxf(mt, __shfl_xor_sync(0xffffffffu, mt, ms));
        float rs = 0.f;
#pragma unroll
        for (int c = 0; c < 4; c++) { s[r][c] = __expf(s[r][c] - mt); rs += s[r][c]; }
#pragma unroll
        for (int ms = 8; ms >= 1; ms >>= 1)
            rs += __shfl_xor_sync(0xffffffffu, rs, ms);
        const float inv = 1.f / rs;
        const int t = t0 + ty + 16*r;
        const size_t so = ((size_t)bh * T_ + t) * 64;
#pragma unroll
        for (int c = 0; c < 4; c++) {
            const float p = s[r][c] * inv;
            sP[(ty + 16*r) * S2P + tx + 16*c] = p;
            s2out[so + tx + 16*c] = p;
        }
    }
    __syncthreads();

    float acc[8][4];
#pragma unroll
    for (int r = 0; r < 8; r++)
#pragma unroll
        for (int c = 0; c < 4; c++) acc[r][c] = 0.f;
#pragma unroll 8
    for (int a = 0; a < 64; a++) {
        float pf[8], cf[4];
#pragma unroll
        for (int r = 0; r < 8; r++) pf[r] = sP[(ty + 16*r) * S2P + a];
#pragma unroll
        for (int c = 0; c < 4; c++) cf[c] = sC1[a * S2P + tx + 16*c];
#pragma unroll
        for (int r = 0; r < 8; r++)
#pragma unroll
            for (int c = 0; c < 4; c++) acc[r][c] = fmaf(pf[r], cf[c], acc[r][c]);
    }
#pragma unroll
    for (int r = 0; r < 8; r++) {
        const int t = t0 + ty + 16*r;
#pragma unroll
        for (int c = 0; c < 4; c++) {
            uint32_t h32, l32;
            split_tf32(acc[r][c], h32, l32);
            const size_t oi = (size_t)(b * T_ + t) * C_ + h * 64 + tx + 16*c;
            c2hi[oi] = __uint_as_float(h32);
            c2lo[oi] = __uint_as_float(l32);
        }
    }
}

// =====================================================================
// launch
// =====================================================================
extern "C" void kernel_launch(void* const* d_in, const int* in_sizes, int n_in,
                              void* d_out, int out_size)
{
    (void)in_sizes; (void)n_in; (void)out_size;
    const float* x     = (const float*)d_in[0];
    const float* Wqkv  = (const float*)d_in[1];
    const float* bqkv  = (const float*)d_in[2];
    const float* Wq    = (const float*)d_in[3];
    const float* bq    = (const float*)d_in[4];
    const float* Wk    = (const float*)d_in[5];
    const float* bk    = (const float*)d_in[6];
    const float* Wv    = (const float*)d_in[7];
    const float* bv    = (const float*)d_in[8];
    const float* ag    = (const float*)d_in[9];
    const float* Wout  = (const float*)d_in[10];
    const float* bout  = (const float*)d_in[11];
    const float* Wproj = (const float*)d_in[12];
    const float* bproj = (const float*)d_in[13];
    float* out = (float*)d_out;

    float *qkv, *w2, *b2, *xs, *c2s, *qa, *pm, *pl, *pacc, *c1, *wcomb, *bcomb;
    cudaGetSymbolAddress((void**)&qkv,   g_qkv);
    cudaGetSymbolAddress((void**)&w2,    g_w2);
    cudaGetSymbolAddress((void**)&b2,    g_b2);
    cudaGetSymbolAddress((void**)&xs,    g_xs);
    cudaGetSymbolAddress((void**)&c2s,   g_c2s);
    cudaGetSymbolAddress((void**)&qa,    g_qa);
    cudaGetSymbolAddress((void**)&pm,    g_pm);
    cudaGetSymbolAddress((void**)&pl,    g_pl);
    cudaGetSymbolAddress((void**)&pacc,  g_pacc);
    cudaGetSymbolAddress((void**)&c1,    g_c1);
    cudaGetSymbolAddress((void**)&wcomb, g_wcomb);
    cudaGetSymbolAddress((void**)&bcomb, g_bcomb);

    const size_t XPL = (size_t)BT_ * C_;     // x / c2 plane size

    cudaFuncSetAttribute(gemm_as_kernel, cudaFuncAttributeMaxDynamicSharedMemorySize, AS_SMEM);
    cudaFuncSetAttribute(gemm_tf32_nn_kernel, cudaFuncAttributeMaxDynamicSharedMemorySize, G_SMEM);
    cudaFuncSetAttribute(stage1_kernel, cudaFuncAttributeMaxDynamicSharedMemorySize, S1_SMEM);
    cudaFuncSetAttribute(stage2_kernel, cudaFuncAttributeMaxDynamicSharedMemorySize, S2_SMEM);

    // 0. fold per-head Wk/Wv into Wqkv (W2, b2); split x into tf32 hi/lo planes
    copyq_kernel<<<C_ * C_ / (256 * 4), 256>>>(Wqkv, w2);
    wfold_kernel<<<dim3(C_/64, 2*NH_), 256>>>(Wqkv, Wk, Wv, w2);
    b2fold_kernel<<<C3_/256, 256>>>(bqkv, Wk, bk, Wv, bv, b2);
    split_kernel<<<(int)(XPL / 1024), 256>>>(x, xs, xs + XPL);
    // 1. qkv = x @ W2^T + b2  ->  [q | k_a | v_a]   (A-pre-split tensor-core GEMM)
    gemm_as_kernel<<<dim3(C3_/128, BT_/128), 256, AS_SMEM>>>(
        xs, xs + XPL, w2, b2, qkv, BT_, C3_, C_);
    // 2. q_a (per-head), combined bias, combined weight wcomb = Wproj @ Wout
    qa_kernel<<<NH_, 256>>>(ag, Wq, bq, qa);
    bcomb_kernel<<<C_/256, 256>>>(Wproj, bout, bproj, bcomb);
    gemm_tf32_nn_kernel<<<dim3(C_/128, C_/128), 256, G_SMEM>>>(Wproj, Wout, wcomb, C_, C_, C_);
    // 3. stage-1 attention (pre-projected k_a/v_a, split-T online softmax)
    stage1_kernel<<<dim3(NCHUNK_, BH_), 256, S1_SMEM>>>(qkv, qa, pm, pl, pacc);
    s1combine_kernel<<<BH_, 256>>>(pm, pl, pacc, c1);
    // 4. stage-2 attention -> s2 (output #2) + c2 (hi/lo split planes)
    stage2_kernel<<<dim3(T_/128, BH_), 256, S2_SMEM>>>(
        qkv, c1, out + (size_t)BT_ * C_, c2s, c2s + XPL);
    // 5. y = c2 @ (Wproj@Wout)^T + b'  -> output #1  (A-pre-split tensor-core GEMM)
    gemm_as_kernel<<<dim3(C_/128, BT_/128), 256, AS_SMEM>>>(
        c2s, c2s + XPL, wcomb, bcomb, out, BT_, C_, C_);
}